// round 4
// baseline (speedup 1.0000x reference)
#include <cuda_runtime.h>
#include <cstdint>

// Problem constants
#define D       256
#define BATCH   1024
#define TSTEPS  1024
#define CHUNK   128
#define NJ      (TSTEPS / CHUNK)   // 8 checkpoints
#define MAT     (D * D)            // 65536 elements per 256x256 matrix

// ---------------------------------------------------------------------------
// Static device scratch (no allocations allowed)
// ---------------------------------------------------------------------------
__device__ float g_A [MAT];                 // A = kernel * DT
__device__ float g_T1[MAT];                 // Taylor term ping
__device__ float g_T2[MAT];                 // Taylor term pong
__device__ float g_P [(CHUNK + 1) * MAT];   // P[i] = E^i, i = 1..128 (index 0 unused)  ~33.8 MB
__device__ float g_Z [NJ * BATCH * D];      // Z[j] = z0 @ E^(128 j)                    ~8.4 MB

// ---------------------------------------------------------------------------
// Packed f32x2 helpers (ptxas will not auto-fuse FFMA2; must be PTX)
// ---------------------------------------------------------------------------
__device__ __forceinline__ void fma2(unsigned long long& d,
                                     unsigned long long a,
                                     unsigned long long b) {
    asm("fma.rn.f32x2 %0, %1, %2, %0;" : "+l"(d) : "l"(a), "l"(b));
}
__device__ __forceinline__ unsigned long long dup2(float x) {
    unsigned long long r;
    asm("mov.b64 %0, {%1, %1};" : "=l"(r) : "f"(x));
    return r;
}

// ---------------------------------------------------------------------------
// prep: A = kernel*DT ; E(=P[1]) = I + A ; T1 = A ; Z[0] = z0
// grid: BATCH*D/256 = 1024 blocks x 256 threads
// ---------------------------------------------------------------------------
__global__ void prep_kernel(const float* __restrict__ z0,
                            const float* __restrict__ kern) {
    int idx = blockIdx.x * 256 + threadIdx.x;      // 0 .. 262143
    g_Z[idx] = z0[idx];
    if (idx < MAT) {
        float a = kern[idx] * 0.01f;
        g_A[idx]  = a;
        g_T1[idx] = a;
        int r = idx >> 8, c = idx & 255;
        g_P[MAT + idx] = a + (r == c ? 1.0f : 0.0f);
    }
}

// ---------------------------------------------------------------------------
// One Taylor term: Tout = (Tin @ A) / k ; E += Tout.  block = one row.
// ---------------------------------------------------------------------------
__global__ void taylor_kernel(int pp, float inv) {
    const float* Tin  = pp ? g_T2 : g_T1;
    float*       Tout = pp ? g_T1 : g_T2;
    int r = blockIdx.x, c = threadIdx.x;
    __shared__ float row[D];
    row[c] = Tin[r * D + c];
    __syncthreads();
    float s = 0.f;
#pragma unroll 8
    for (int k = 0; k < D; ++k) s += row[k] * g_A[k * D + c];
    s *= inv;
    Tout[r * D + c]     = s;
    g_P[MAT + r * D + c] += s;
}

// ---------------------------------------------------------------------------
// Tiled fp32 GEMM (f32x2 accumulate), C = A @ B, K = 256 fixed.
//   BM=128, BN=128, BK=16, 256 threads, 8x8 microtile, accum packed along N.
// MODE_PB   : power doubling   P[p0+i] = P[p0] @ P[i],  i = 1 + blockIdx.z
// MODE_PLAIN: checkpoint chain Z[p0+1] = Z[p0] @ P[128]
// MODE_FILL : out[:, 128j + z, :] = Z_j @ P[z+1]   (row gm -> j = gm>>10)
// ---------------------------------------------------------------------------
enum { MODE_PLAIN = 0, MODE_PB = 1, MODE_FILL = 2 };

template <int MODE>
__global__ __launch_bounds__(256, 2)
void gemm_kernel(int p0, float* __restrict__ outp) {
    const float* A;
    const float* B;
    float*       C;
    if (MODE == MODE_PB) {
        int i = 1 + blockIdx.z;
        A = g_P + (size_t)p0 * MAT;
        B = g_P + (size_t)i * MAT;
        C = g_P + (size_t)(p0 + i) * MAT;
    } else if (MODE == MODE_FILL) {
        A = g_Z;
        B = g_P + (size_t)(1 + blockIdx.z) * MAT;
        C = outp;
    } else {
        A = g_Z + (size_t)p0 * (BATCH * D);
        B = g_P + (size_t)CHUNK * MAT;
        C = g_Z + (size_t)(p0 + 1) * (BATCH * D);
    }

    const int tid = threadIdx.x;
    const int tx = tid & 15, ty = tid >> 4;
    const int blockM = blockIdx.y * 128;
    const int blockN = blockIdx.x * 128;

    __shared__ __align__(16) float As[16][132];  // transposed A tile, padded
    __shared__ __align__(16) float Bs[16][128];

    unsigned long long acc[8][4];
#pragma unroll
    for (int i = 0; i < 8; ++i)
#pragma unroll
        for (int j = 0; j < 4; ++j) acc[i][j] = 0ull;

    // A tile load map: 128 rows x 16 cols = 512 float4; 2 per thread
    const int am = tid >> 2;             // 0..63 (and +64)
    const int ak = (tid & 3) * 4;        // 0,4,8,12
    // B tile load map: 16 rows x 128 cols = 512 float4; 2 per thread
    const int bk = tid >> 5;             // 0..7 (and +8)
    const int bn = (tid & 31) * 4;       // 0..124

    const float* Ap0 = A + (size_t)(blockM + am) * D + ak;
    const float* Ap1 = Ap0 + (size_t)64 * D;
    const float* Bp0 = B + (size_t)bk * D + blockN + bn;
    const float* Bp1 = Bp0 + (size_t)8 * D;

    float4 pa0 = *(const float4*)Ap0;
    float4 pa1 = *(const float4*)Ap1;
    float4 pb0 = *(const float4*)Bp0;
    float4 pb1 = *(const float4*)Bp1;

    for (int kt = 0; kt < 16; ++kt) {
        // commit prefetched tile to smem (A transposed)
        As[ak + 0][am]      = pa0.x; As[ak + 1][am]      = pa0.y;
        As[ak + 2][am]      = pa0.z; As[ak + 3][am]      = pa0.w;
        As[ak + 0][am + 64] = pa1.x; As[ak + 1][am + 64] = pa1.y;
        As[ak + 2][am + 64] = pa1.z; As[ak + 3][am + 64] = pa1.w;
        *(float4*)&Bs[bk][bn]     = pb0;
        *(float4*)&Bs[bk + 8][bn] = pb1;
        __syncthreads();

        if (kt < 15) {   // overlap next-tile LDG with compute
            pa0 = *(const float4*)(Ap0 + (kt + 1) * 16);
            pa1 = *(const float4*)(Ap1 + (kt + 1) * 16);
            pb0 = *(const float4*)(Bp0 + (size_t)(kt + 1) * 16 * D);
            pb1 = *(const float4*)(Bp1 + (size_t)(kt + 1) * 16 * D);
        }

#pragma unroll
        for (int kk = 0; kk < 16; ++kk) {
            float4 a0 = *(const float4*)&As[kk][ty * 8];
            float4 a1 = *(const float4*)&As[kk][ty * 8 + 4];
            ulonglong2 bq0 = *(const ulonglong2*)&Bs[kk][tx * 8];      // n-pairs, bitwise free
            ulonglong2 bq1 = *(const ulonglong2*)&Bs[kk][tx * 8 + 4];
            float a[8] = {a0.x, a0.y, a0.z, a0.w, a1.x, a1.y, a1.z, a1.w};
#pragma unroll
            for (int i = 0; i < 8; ++i) {
                unsigned long long aa = dup2(a[i]);   // alu pipe; dual-issues vs fma pipe
                fma2(acc[i][0], aa, bq0.x);
                fma2(acc[i][1], aa, bq0.y);
                fma2(acc[i][2], aa, bq1.x);
                fma2(acc[i][3], aa, bq1.y);
            }
        }
        __syncthreads();
    }

    // epilogue: packed pairs are bitwise two contiguous floats -> 16B stores
#pragma unroll
    for (int i = 0; i < 8; ++i) {
        int gm = blockM + ty * 8 + i;
        float* crow;
        if (MODE == MODE_FILL) {
            int j = gm >> 10;               // checkpoint index
            int b = gm & 1023;              // batch row
            int t = j * CHUNK + blockIdx.z; // time step
            crow = C + ((size_t)b * TSTEPS + t) * D + blockN + tx * 8;
        } else {
            crow = C + (size_t)gm * D + blockN + tx * 8;
        }
        ulonglong2 v0; v0.x = acc[i][0]; v0.y = acc[i][1];
        ulonglong2 v1; v1.x = acc[i][2]; v1.y = acc[i][3];
        *(ulonglong2*)(crow)     = v0;
        *(ulonglong2*)(crow + 4) = v1;
    }
}

// ---------------------------------------------------------------------------
// Launch: expm (Taylor-8) -> power doubling (7) -> checkpoint chain (7) -> fill
// ---------------------------------------------------------------------------
extern "C" void kernel_launch(void* const* d_in, const int* in_sizes, int n_in,
                              void* d_out, int out_size) {
    const float* z0   = (const float*)d_in[0];   // [1024, 256]
    const float* kern = (const float*)d_in[1];   // [256, 256]
    float* out = (float*)d_out;                  // [1024, 1024, 256]
    (void)in_sizes; (void)n_in; (void)out_size;

    // 1) A, E = I + A, Z0 = z0
    prep_kernel<<<(BATCH * D) / 256, 256>>>(z0, kern);

    // 2) Taylor terms 2..8 of expm(A); ||A||_2 ~ 0.02 so 8 terms >> fp32 eps
    int pp = 0;
    for (int k = 2; k <= 8; ++k) {
        taylor_kernel<<<D, D>>>(pp, 1.0f / (float)k);
        pp ^= 1;
    }

    // 3) Powers P[1..128] by batched doubling: 7 launches
    for (int m = 1; m < CHUNK; m <<= 1) {
        dim3 g(2, 2, m);
        gemm_kernel<MODE_PB><<<g, 256>>>(m, nullptr);
    }

    // 4) Checkpoints Z[1..7]: Z[j+1] = Z[j] @ P[128]
    for (int j = 0; j < NJ - 1; ++j) {
        dim3 g(2, BATCH / 128, 1);
        gemm_kernel<MODE_PLAIN><<<g, 256>>>(j, nullptr);
    }

    // 5) Parallel fill: out[:, 128 j + i, :] = Z_j @ P[i+1]  (16384 CTAs)
    dim3 gf(2, (NJ * BATCH) / 128, CHUNK);
    gemm_kernel<MODE_FILL><<<gf, 256>>>(0, out);
}

// round 8
// speedup vs baseline: 1.2269x; 1.2269x over previous
#include <cuda_runtime.h>
#include <cuda_bf16.h>
#include <cstdint>

// Problem constants
#define D       256
#define BATCH   1024
#define TSTEPS  1024
#define CHUNK   128
#define NJ      (TSTEPS / CHUNK)   // 8 checkpoints
#define MAT     (D * D)

// ---------------------------------------------------------------------------
// Static device scratch
// ---------------------------------------------------------------------------
__device__ float g_A [MAT];
__device__ float g_T1[MAT];
__device__ float g_T2[MAT];
__device__ float g_P [(CHUNK + 1) * MAT];     // P[i] = E^i fp32, i=1..128
__device__ float g_Z [NJ * BATCH * D];        // fp32 checkpoints
// bf16 hi/lo, pre-tiled + pre-swizzled (XOR-8 on 16B groups) for ldmatrix:
// g_PB: [z(128)][kchunk(4)][half(2)][2048 x uint4]  (B^T tiles: 256 n-rows x 128B)
__device__ uint4 g_PB[128 * 4 * 2 * 2048];    // 32 MB
// g_ZB: [mtile(64)][kchunk(4)][half(2)][1024 x uint4] (A tiles: 128 m-rows x 128B)
__device__ uint4 g_ZB[64 * 4 * 2 * 1024];     // 8 MB

// ---------------------------------------------------------------------------
// Helpers
// ---------------------------------------------------------------------------
__device__ __forceinline__ uint32_t smem_u32(const void* p) {
    uint32_t a;
    asm("{ .reg .u64 t; cvta.to.shared.u64 t, %1; cvt.u32.u64 %0, t; }"
        : "=r"(a) : "l"(p));
    return a;
}
// f32x2 helpers for the fp32 chain GEMM
__device__ __forceinline__ void fma2(unsigned long long& d,
                                     unsigned long long a,
                                     unsigned long long b) {
    asm("fma.rn.f32x2 %0, %1, %2, %0;" : "+l"(d) : "l"(a), "l"(b));
}
__device__ __forceinline__ unsigned long long dup2(float x) {
    unsigned long long r;
    asm("mov.b64 %0, {%1, %1};" : "=l"(r) : "f"(x));
    return r;
}
// HMMA path (all legal on plain sm_103 target)
__device__ __forceinline__ void ldsm4(uint32_t* r, uint32_t addr) {
    asm volatile("ldmatrix.sync.aligned.m8n8.x4.shared.b16 {%0,%1,%2,%3}, [%4];"
                 : "=r"(r[0]), "=r"(r[1]), "=r"(r[2]), "=r"(r[3]) : "r"(addr));
}
__device__ __forceinline__ void mma16816(float* d, const uint32_t* a,
                                         uint32_t b0, uint32_t b1) {
    asm volatile(
        "mma.sync.aligned.m16n8k16.row.col.f32.bf16.bf16.f32 "
        "{%0,%1,%2,%3}, {%4,%5,%6,%7}, {%8,%9}, {%0,%1,%2,%3};"
        : "+f"(d[0]), "+f"(d[1]), "+f"(d[2]), "+f"(d[3])
        : "r"(a[0]), "r"(a[1]), "r"(a[2]), "r"(a[3]), "r"(b0), "r"(b1));
}
#define CP16(dst, src) \
    asm volatile("cp.async.cg.shared.global [%0], [%1], 16;" \
                 :: "r"(dst), "l"(src))
#define CP_COMMIT() asm volatile("cp.async.commit_group;" ::: "memory")
#define CP_WAIT1()  asm volatile("cp.async.wait_group 1;" ::: "memory")
#define CP_WAIT0()  asm volatile("cp.async.wait_group 0;" ::: "memory")

// ---------------------------------------------------------------------------
// prep: A = kernel*DT ; P[1] = I + A ; T1 = A ; Z[0] = z0
// ---------------------------------------------------------------------------
__global__ void prep_kernel(const float* __restrict__ z0,
                            const float* __restrict__ kern) {
    int idx = blockIdx.x * 256 + threadIdx.x;
    g_Z[idx] = z0[idx];
    if (idx < MAT) {
        float a = kern[idx] * 0.01f;
        g_A[idx]  = a;
        g_T1[idx] = a;
        int r = idx >> 8, c = idx & 255;
        g_P[MAT + idx] = a + (r == c ? 1.0f : 0.0f);
    }
}

// ---------------------------------------------------------------------------
// Taylor term: Tout = (Tin @ A)/k ; E += Tout.
// ---------------------------------------------------------------------------
__global__ void taylor_kernel(int pp, float inv) {
    const float* Tin  = pp ? g_T2 : g_T1;
    float*       Tout = pp ? g_T1 : g_T2;
    int r = blockIdx.x, c = threadIdx.x;
    __shared__ float row[D];
    row[c] = Tin[r * D + c];
    __syncthreads();
    float s0 = 0.f, s1 = 0.f, s2 = 0.f, s3 = 0.f;
#pragma unroll 4
    for (int k = 0; k < D; k += 4) {
        s0 += row[k + 0] * g_A[(k + 0) * D + c];
        s1 += row[k + 1] * g_A[(k + 1) * D + c];
        s2 += row[k + 2] * g_A[(k + 2) * D + c];
        s3 += row[k + 3] * g_A[(k + 3) * D + c];
    }
    float s = ((s0 + s1) + (s2 + s3)) * inv;
    Tout[r * D + c] = s;
    g_P[MAT + r * D + c] += s;
}

// ---------------------------------------------------------------------------
// fp32 FFMA2 GEMM for powers (MODE_PB) and checkpoint chain (MODE_PLAIN).
// BM=128, BN=128, BK=16, K=256, 256 threads, 8x8 microtile.
// ---------------------------------------------------------------------------
enum { MODE_PLAIN = 0, MODE_PB = 1 };

template <int MODE>
__global__ __launch_bounds__(256, 2)
void gemm_kernel(int p0) {
    const float* A;
    const float* B;
    float*       C;
    if (MODE == MODE_PB) {
        int i = 1 + blockIdx.z;
        A = g_P + (size_t)p0 * MAT;
        B = g_P + (size_t)i * MAT;
        C = g_P + (size_t)(p0 + i) * MAT;
    } else {
        A = g_Z + (size_t)p0 * (BATCH * D);
        B = g_P + (size_t)CHUNK * MAT;
        C = g_Z + (size_t)(p0 + 1) * (BATCH * D);
    }

    const int tid = threadIdx.x;
    const int tx = tid & 15, ty = tid >> 4;
    const int blockM = blockIdx.y * 128;
    const int blockN = blockIdx.x * 128;

    __shared__ __align__(16) float As[16][132];
    __shared__ __align__(16) float Bs[16][128];

    unsigned long long acc[8][4];
#pragma unroll
    for (int i = 0; i < 8; ++i)
#pragma unroll
        for (int j = 0; j < 4; ++j) acc[i][j] = 0ull;

    const int am = tid >> 2;
    const int ak = (tid & 3) * 4;
    const int bk = tid >> 5;
    const int bn = (tid & 31) * 4;

    const float* Ap0 = A + (size_t)(blockM + am) * D + ak;
    const float* Ap1 = Ap0 + (size_t)64 * D;
    const float* Bp0 = B + (size_t)bk * D + blockN + bn;
    const float* Bp1 = Bp0 + (size_t)8 * D;

    float4 pa0 = *(const float4*)Ap0;
    float4 pa1 = *(const float4*)Ap1;
    float4 pb0 = *(const float4*)Bp0;
    float4 pb1 = *(const float4*)Bp1;

    for (int kt = 0; kt < 16; ++kt) {
        As[ak + 0][am]      = pa0.x; As[ak + 1][am]      = pa0.y;
        As[ak + 2][am]      = pa0.z; As[ak + 3][am]      = pa0.w;
        As[ak + 0][am + 64] = pa1.x; As[ak + 1][am + 64] = pa1.y;
        As[ak + 2][am + 64] = pa1.z; As[ak + 3][am + 64] = pa1.w;
        *(float4*)&Bs[bk][bn]     = pb0;
        *(float4*)&Bs[bk + 8][bn] = pb1;
        __syncthreads();

        if (kt < 15) {
            pa0 = *(const float4*)(Ap0 + (kt + 1) * 16);
            pa1 = *(const float4*)(Ap1 + (kt + 1) * 16);
            pb0 = *(const float4*)(Bp0 + (size_t)(kt + 1) * 16 * D);
            pb1 = *(const float4*)(Bp1 + (size_t)(kt + 1) * 16 * D);
        }

#pragma unroll
        for (int kk = 0; kk < 16; ++kk) {
            float4 a0 = *(const float4*)&As[kk][ty * 8];
            float4 a1 = *(const float4*)&As[kk][ty * 8 + 4];
            ulonglong2 bq0 = *(const ulonglong2*)&Bs[kk][tx * 8];
            ulonglong2 bq1 = *(const ulonglong2*)&Bs[kk][tx * 8 + 4];
            float a[8] = {a0.x, a0.y, a0.z, a0.w, a1.x, a1.y, a1.z, a1.w};
#pragma unroll
            for (int i = 0; i < 8; ++i) {
                unsigned long long aa = dup2(a[i]);
                fma2(acc[i][0], aa, bq0.x);
                fma2(acc[i][1], aa, bq0.y);
                fma2(acc[i][2], aa, bq1.x);
                fma2(acc[i][3], aa, bq1.y);
            }
        }
        __syncthreads();
    }

#pragma unroll
    for (int i = 0; i < 8; ++i) {
        int gm = blockM + ty * 8 + i;
        float* crow = C + (size_t)gm * D + blockN + tx * 8;
        ulonglong2 v0; v0.x = acc[i][0]; v0.y = acc[i][1];
        ulonglong2 v1; v1.x = acc[i][2]; v1.y = acc[i][3];
        *(ulonglong2*)(crow)     = v0;
        *(ulonglong2*)(crow + 4) = v1;
    }
}

// ---------------------------------------------------------------------------
// bf16 hi/lo split + pre-tile + pre-swizzle conversions
// ---------------------------------------------------------------------------
__device__ __forceinline__ void split_bf16(float v, unsigned short& h, unsigned short& l) {
    __nv_bfloat16 hb = __float2bfloat16(v);
    float r = v - __bfloat162float(hb);
    __nv_bfloat16 lb = __float2bfloat16(r);
    h = reinterpret_cast<unsigned short&>(hb);
    l = reinterpret_cast<unsigned short&>(lb);
}
__device__ __forceinline__ uint32_t pack2(unsigned short a, unsigned short b) {
    return (uint32_t)a | ((uint32_t)b << 16);
}

// B tiles: stored[n][k] = P^(z+1)[k][n], 256 n-rows x 128B (64 k bf16), XOR-8 swizzle
__global__ void convB_kernel() {
    int u = blockIdx.x * 256 + threadIdx.x;       // 0..1048575
    int z   = u >> 13;
    int rem = u & 8191;
    int c   = rem >> 11;
    int u2  = rem & 2047;
    int n   = u2 & 255;                           // n fastest -> coalesced reads
    int g   = u2 >> 8;                            // 16B group within row (0..7)
    const float* src = g_P + (size_t)(z + 1) * MAT + (size_t)(c * 64 + g * 8) * D + n;
    unsigned short h[8], l[8];
#pragma unroll
    for (int e = 0; e < 8; ++e) split_bf16(src[(size_t)e * D], h[e], l[e]);
    uint4 H, L;
    H.x = pack2(h[0], h[1]); H.y = pack2(h[2], h[3]);
    H.z = pack2(h[4], h[5]); H.w = pack2(h[6], h[7]);
    L.x = pack2(l[0], l[1]); L.y = pack2(l[2], l[3]);
    L.z = pack2(l[4], l[5]); L.w = pack2(l[6], l[7]);
    size_t base = ((size_t)(z * 4 + c) * 2) * 2048;
    int du = n * 8 + (g ^ (n & 7));
    g_PB[base + du]        = H;
    g_PB[base + 2048 + du] = L;
}

// A tiles: stored[m][k] = Z[m][k], 128 m-rows x 128B per tile, XOR-8 swizzle
__global__ void convA_kernel() {
    int u = blockIdx.x * 256 + threadIdx.x;       // 0..262143
    int tile = u >> 12;
    int rem  = u & 4095;
    int c    = rem >> 10;
    int u2   = rem & 1023;
    int row  = u2 >> 3;
    int g    = u2 & 7;
    int m = tile * 128 + row;
    const float* src = g_Z + (size_t)m * D + c * 64 + g * 8;
    unsigned short h[8], l[8];
#pragma unroll
    for (int e = 0; e < 8; ++e) split_bf16(src[e], h[e], l[e]);
    uint4 H, L;
    H.x = pack2(h[0], h[1]); H.y = pack2(h[2], h[3]);
    H.z = pack2(h[4], h[5]); H.w = pack2(h[6], h[7]);
    L.x = pack2(l[0], l[1]); L.y = pack2(l[2], l[3]);
    L.z = pack2(l[4], l[5]); L.w = pack2(l[6], l[7]);
    size_t base = ((size_t)(tile * 4 + c) * 2) * 1024;
    int du = row * 8 + (g ^ (row & 7));
    g_ZB[base + du]        = H;
    g_ZB[base + 1024 + du] = L;
}

// ---------------------------------------------------------------------------
// HMMA fill kernel: out[:, 128j+z, :] = Z_j @ P^(z+1), 3-pass bf16 split.
// grid (128 tiles, 128 z), 256 threads, BM=128 BN=128 K=256.
// cp.async double-buffered K-chunks of 64 (Ah/Al/Bh/Bl per stage = 64KB).
// 8 warps, warp tile 64x32, mma.sync.m16n8k16 + ldmatrix (swizzle pre-applied).
// ---------------------------------------------------------------------------
#define STAGE_BYTES 65536
#define FILL_SMEM   (2 * STAGE_BYTES)

__global__ __launch_bounds__(256, 1)
void fill_kernel(float* __restrict__ out) {
    extern __shared__ __align__(128) char sm[];
    const uint32_t sbase = smem_u32(sm);
    const int tid = threadIdx.x;
    const int tile_m = blockIdx.x >> 1, tile_n = blockIdx.x & 1;
    const int z = blockIdx.y;
    const int wid = tid >> 5, lid = tid & 31;
    const int warp_m = wid >> 2, warp_n = wid & 3;

    // stage layout: Ah [0,16K) Al [16K,32K) Bh [32K,48K) Bl [48K,64K)
    auto issue = [&](int c, int buf) {
        const char* a0 = (const char*)(g_ZB + ((size_t)(tile_m * 4 + c) * 2) * 1024)
                         + tid * 16;
        const char* b0 = (const char*)(g_PB + ((size_t)(z * 4 + c) * 2) * 2048
                                       + tile_n * 1024) + tid * 16;
        uint32_t d = sbase + buf * STAGE_BYTES + tid * 16;
#pragma unroll
        for (int q = 0; q < 4; ++q) {
            CP16(d + q * 4096,         a0 + q * 4096);            // Ah
            CP16(d + 16384 + q * 4096, a0 + 16384 + q * 4096);    // Al
            CP16(d + 32768 + q * 4096, b0 + q * 4096);            // Bh
            CP16(d + 49152 + q * 4096, b0 + 32768 + q * 4096);    // Bl
        }
        CP_COMMIT();
    };

    float acc[4][4][4];
#pragma unroll
    for (int i = 0; i < 4; ++i)
#pragma unroll
        for (int j = 0; j < 4; ++j)
#pragma unroll
            for (int q = 0; q < 4; ++q) acc[i][j][q] = 0.f;

    // per-lane ldmatrix address components (rows are base8-aligned => row&7 == lr)
    const int lq = lid >> 3, lr = lid & 7;
    const uint32_t a_row = warp_m * 64 + (lq & 1) * 8 + lr;
    const uint32_t b_row = warp_n * 32 + (lq & 1) * 8 + lr;
    const int gh = lq >> 1;

    issue(0, 0);
    for (int c = 0; c < 4; ++c) {
        if (c < 3) { issue(c + 1, (c + 1) & 1); CP_WAIT1(); }
        else       { CP_WAIT0(); }
        __syncthreads();

        const uint32_t ab  = sbase + (c & 1) * STAGE_BYTES;
        const uint32_t alb = ab + 16384, bb = ab + 32768, blb = ab + 49152;
#pragma unroll
        for (int ks = 0; ks < 4; ++ks) {
            const uint32_t gx = ((uint32_t)(ks * 2 + gh) ^ lr) * 16;
            uint32_t ah[4][4], al[4][4], bh[2][4], bl[2][4];
#pragma unroll
            for (int mf = 0; mf < 4; ++mf) {
                uint32_t off = (a_row + mf * 16) * 128 + gx;
                ldsm4(ah[mf], ab + off);
                ldsm4(al[mf], alb + off);
            }
#pragma unroll
            for (int nf = 0; nf < 2; ++nf) {
                uint32_t off = (b_row + nf * 16) * 128 + gx;
                ldsm4(bh[nf], bb + off);
                ldsm4(bl[nf], blb + off);
            }
#pragma unroll
            for (int mf = 0; mf < 4; ++mf)
#pragma unroll
                for (int j = 0; j < 4; ++j) {
                    const int n2 = j >> 1, e = j & 1;
                    mma16816(acc[mf][j], ah[mf], bh[n2][e], bh[n2][e + 2]);
                    mma16816(acc[mf][j], ah[mf], bl[n2][e], bl[n2][e + 2]);
                    mma16816(acc[mf][j], al[mf], bh[n2][e], bh[n2][e + 2]);
                }
        }
        __syncthreads();
    }

    // epilogue: whole CTA tile has constant t; rows map to batch
    const int t  = (tile_m >> 3) * CHUNK + z;
    const int b0 = (tile_m & 7) * 128 + warp_m * 64;
    const int nb = tile_n * 128 + warp_n * 32 + (lid & 3) * 2;
    const int rr = lid >> 2;
#pragma unroll
    for (int mf = 0; mf < 4; ++mf)
#pragma unroll
        for (int j = 0; j < 4; ++j) {
            int b = b0 + mf * 16 + rr;
            float* p0 = out + ((size_t)b * TSTEPS + t) * D + nb + j * 8;
            float* p1 = out + ((size_t)(b + 8) * TSTEPS + t) * D + nb + j * 8;
            *(float2*)p0 = make_float2(acc[mf][j][0], acc[mf][j][1]);
            *(float2*)p1 = make_float2(acc[mf][j][2], acc[mf][j][3]);
        }
}

// ---------------------------------------------------------------------------
// Launch sequence
// ---------------------------------------------------------------------------
extern "C" void kernel_launch(void* const* d_in, const int* in_sizes, int n_in,
                              void* d_out, int out_size) {
    const float* z0   = (const float*)d_in[0];
    const float* kern = (const float*)d_in[1];
    float* out = (float*)d_out;
    (void)in_sizes; (void)n_in; (void)out_size;

    // 1) A, P[1] = I + A, Z0 = z0
    prep_kernel<<<(BATCH * D) / 256, 256>>>(z0, kern);

    // 2) Taylor terms 2..6 (||A|| ~ 0.02 -> term7 ~ 2.5e-16)
    int pp = 0;
    for (int k = 2; k <= 6; ++k) {
        taylor_kernel<<<D, D>>>(pp, 1.0f / (float)k);
        pp ^= 1;
    }

    // 3) Powers P[1..128] by batched doubling (fp32 exact chain)
    for (int m = 1; m < CHUNK; m <<= 1) {
        dim3 g(2, 2, m);
        gemm_kernel<MODE_PB><<<g, 256>>>(m);
    }

    // 4) bf16 hi/lo tiling of all P powers (B operands, transposed)
    convB_kernel<<<4096, 256>>>();

    // 5) Checkpoint chain Z[1..7] (fp32 exact)
    for (int j = 0; j < NJ - 1; ++j) {
        dim3 g(2, BATCH / 128, 1);
        gemm_kernel<MODE_PLAIN><<<g, 256>>>(j);
    }

    // 6) bf16 hi/lo tiling of checkpoints (A operands)
    convA_kernel<<<1024, 256>>>();

    // 7) HMMA fill
    cudaFuncSetAttribute(fill_kernel,
                         cudaFuncAttributeMaxDynamicSharedMemorySize, FILL_SMEM);
    dim3 gf(128, 128);
    fill_kernel<<<gf, 256, FILL_SMEM>>>(out);
}

// round 11
// speedup vs baseline: 2.6804x; 2.1846x over previous
#include <cuda_runtime.h>
#include <cuda_bf16.h>
#include <cuda_fp16.h>
#include <cstdint>

// Problem constants
#define D       256
#define BATCH   1024
#define TSTEPS  1024
#define CHUNK   128
#define NJ      (TSTEPS / CHUNK)   // 8 checkpoints
#define MAT     (D * D)

// ---------------------------------------------------------------------------
// Static device scratch
// ---------------------------------------------------------------------------
__device__ float g_A [MAT];
__device__ float g_T1[MAT];
__device__ float g_T2[MAT];
__device__ float g_P [(CHUNK + 1) * MAT];     // P[i] = E^i fp32, i=1..128
__device__ float g_Z [NJ * BATCH * D];        // fp32 checkpoints
// fp16 operands, pre-tiled + pre-swizzled (XOR-8 on 16B groups) for ldmatrix:
// g_PB: [z(128)][kchunk(4)][half(2)][2048 x uint4]  (B^T tiles: 256 n-rows x 128B)
//       values scaled by 2^-2; half 0 = hi, half 1 = lo of fp16 split
__device__ uint4 g_PB[128 * 4 * 2 * 2048];    // 32 MB
// g_ZH: [mtile(64)][kchunk(4)][1024 x uint4]  (A tiles: 128 m-rows x 128B)
//       fp16(Z * 2^-6), hi only (asymmetric split)
__device__ uint4 g_ZH[64 * 4 * 1024];         // 4 MB

// ---------------------------------------------------------------------------
// Helpers
// ---------------------------------------------------------------------------
__device__ __forceinline__ uint32_t smem_u32(const void* p) {
    uint32_t a;
    asm("{ .reg .u64 t; cvta.to.shared.u64 t, %1; cvt.u32.u64 %0, t; }"
        : "=r"(a) : "l"(p));
    return a;
}
// f32x2 helpers for the fp32 chain GEMM
__device__ __forceinline__ void fma2(unsigned long long& d,
                                     unsigned long long a,
                                     unsigned long long b) {
    asm("fma.rn.f32x2 %0, %1, %2, %0;" : "+l"(d) : "l"(a), "l"(b));
}
__device__ __forceinline__ unsigned long long dup2(float x) {
    unsigned long long r;
    asm("mov.b64 %0, {%1, %1};" : "=l"(r) : "f"(x));
    return r;
}
// HMMA path (legal on plain sm_103 target)
__device__ __forceinline__ void ldsm4(uint32_t* r, uint32_t addr) {
    asm volatile("ldmatrix.sync.aligned.m8n8.x4.shared.b16 {%0,%1,%2,%3}, [%4];"
                 : "=r"(r[0]), "=r"(r[1]), "=r"(r[2]), "=r"(r[3]) : "r"(addr));
}
__device__ __forceinline__ void mma16816h(float* d, const uint32_t* a,
                                          uint32_t b0, uint32_t b1) {
    asm volatile(
        "mma.sync.aligned.m16n8k16.row.col.f32.f16.f16.f32 "
        "{%0,%1,%2,%3}, {%4,%5,%6,%7}, {%8,%9}, {%0,%1,%2,%3};"
        : "+f"(d[0]), "+f"(d[1]), "+f"(d[2]), "+f"(d[3])
        : "r"(a[0]), "r"(a[1]), "r"(a[2]), "r"(a[3]), "r"(b0), "r"(b1));
}
#define CP16(dst, src) \
    asm volatile("cp.async.cg.shared.global [%0], [%1], 16;" \
                 :: "r"(dst), "l"(src))
#define CP_COMMIT() asm volatile("cp.async.commit_group;" ::: "memory")
#define CP_WAIT1()  asm volatile("cp.async.wait_group 1;" ::: "memory")
#define CP_WAIT0()  asm volatile("cp.async.wait_group 0;" ::: "memory")

// ---------------------------------------------------------------------------
// prep: A = kernel*DT ; P[1] = I + A ; T1 = A ; Z[0] = z0
// ---------------------------------------------------------------------------
__global__ void prep_kernel(const float* __restrict__ z0,
                            const float* __restrict__ kern) {
    int idx = blockIdx.x * 256 + threadIdx.x;
    g_Z[idx] = z0[idx];
    if (idx < MAT) {
        float a = kern[idx] * 0.01f;
        g_A[idx]  = a;
        g_T1[idx] = a;
        int r = idx >> 8, c = idx & 255;
        g_P[MAT + idx] = a + (r == c ? 1.0f : 0.0f);
    }
}

// ---------------------------------------------------------------------------
// 64x64-tile fp32 FFMA2 GEMM, K=256 fixed, 128 threads, 8x4 microtile.
// M_TAYLOR: Tout = (Tin @ g_A) * scale ; E += Tout   (p0 = ping-pong flag)
// M_PB    : P[p0 + 1 + bz] = P[p0] @ P[1 + bz]
// M_PLAIN : Z[p0+1] = Z[p0] @ P[128]
// ---------------------------------------------------------------------------
enum { M_PLAIN = 0, M_PB = 1, M_TAYLOR = 2 };

template <int MODE>
__global__ __launch_bounds__(128, 8)
void gemm64_kernel(int p0, float scale) {
    const float* A;
    const float* B;
    float*       C;
    if (MODE == M_PB) {
        int i = 1 + blockIdx.z;
        A = g_P + (size_t)p0 * MAT;
        B = g_P + (size_t)i * MAT;
        C = g_P + (size_t)(p0 + i) * MAT;
    } else if (MODE == M_TAYLOR) {
        A = p0 ? g_T2 : g_T1;
        B = g_A;
        C = p0 ? g_T1 : g_T2;
    } else {
        A = g_Z + (size_t)p0 * (BATCH * D);
        B = g_P + (size_t)CHUNK * MAT;
        C = g_Z + (size_t)(p0 + 1) * (BATCH * D);
    }

    const int tid = threadIdx.x;
    const int tx = tid & 15, ty = tid >> 4;        // n: 16x4, m: 8x8
    const int blockM = blockIdx.y * 64;
    const int blockN = blockIdx.x * 64;

    __shared__ __align__(16) float As[16][68];
    __shared__ __align__(16) float Bs[16][64];

    unsigned long long acc[8][2];
#pragma unroll
    for (int i = 0; i < 8; ++i) { acc[i][0] = 0ull; acc[i][1] = 0ull; }

    const int a_r = tid >> 1, a_k = (tid & 1) * 8;   // 64 rows x 16 k
    const int b_k = tid >> 3, b_n = (tid & 7) * 8;   // 16 k x 64 n

    const float* Ap = A + (size_t)(blockM + a_r) * D + a_k;
    const float* Bp = B + (size_t)b_k * D + blockN + b_n;

    float4 pa0 = *(const float4*)Ap;
    float4 pa1 = *(const float4*)(Ap + 4);
    float4 pb0 = *(const float4*)Bp;
    float4 pb1 = *(const float4*)(Bp + 4);

    for (int kt = 0; kt < 16; ++kt) {
        As[a_k + 0][a_r] = pa0.x; As[a_k + 1][a_r] = pa0.y;
        As[a_k + 2][a_r] = pa0.z; As[a_k + 3][a_r] = pa0.w;
        As[a_k + 4][a_r] = pa1.x; As[a_k + 5][a_r] = pa1.y;
        As[a_k + 6][a_r] = pa1.z; As[a_k + 7][a_r] = pa1.w;
        *(float4*)&Bs[b_k][b_n]     = pb0;
        *(float4*)&Bs[b_k][b_n + 4] = pb1;
        __syncthreads();

        if (kt < 15) {
            pa0 = *(const float4*)(Ap + (kt + 1) * 16);
            pa1 = *(const float4*)(Ap + (kt + 1) * 16 + 4);
            pb0 = *(const float4*)(Bp + (size_t)(kt + 1) * 16 * D);
            pb1 = *(const float4*)(Bp + (size_t)(kt + 1) * 16 * D + 4);
        }

#pragma unroll
        for (int kk = 0; kk < 16; ++kk) {
            float4 a0 = *(const float4*)&As[kk][ty * 8];
            float4 a1 = *(const float4*)&As[kk][ty * 8 + 4];
            ulonglong2 bq = *(const ulonglong2*)&Bs[kk][tx * 4];
            float a[8] = {a0.x, a0.y, a0.z, a0.w, a1.x, a1.y, a1.z, a1.w};
#pragma unroll
            for (int i = 0; i < 8; ++i) {
                unsigned long long aa = dup2(a[i]);
                fma2(acc[i][0], aa, bq.x);
                fma2(acc[i][1], aa, bq.y);
            }
        }
        __syncthreads();
    }

#pragma unroll
    for (int i = 0; i < 8; ++i) {
        int row = blockM + ty * 8 + i;
        int col = blockN + tx * 4;
        if (MODE == M_TAYLOR) {
            ulonglong2 v; v.x = acc[i][0]; v.y = acc[i][1];
            float* fv = (float*)&v;
            size_t idx = (size_t)row * D + col;
#pragma unroll
            for (int j = 0; j < 4; ++j) {
                float s = fv[j] * scale;
                C[idx + j] = s;
                g_P[MAT + idx + j] += s;
            }
        } else {
            ulonglong2 v; v.x = acc[i][0]; v.y = acc[i][1];
            *(ulonglong2*)(C + (size_t)row * D + col) = v;
        }
    }
}

// ---------------------------------------------------------------------------
// fp16 conversions, pre-tiled + pre-swizzled
// ---------------------------------------------------------------------------
__device__ __forceinline__ uint32_t packh2(__half a, __half b) {
    __half_raw ar = *(__half_raw*)&a, br = *(__half_raw*)&b;
    return (uint32_t)ar.x | ((uint32_t)br.x << 16);
}

// B tiles: stored[n][k] = P^(z+1)[k][n] * 2^-2, fp16 hi + lo halves
__global__ void convB_kernel() {
    int u = blockIdx.x * 256 + threadIdx.x;       // 0..1048575
    int z   = u >> 13;
    int rem = u & 8191;
    int c   = rem >> 11;
    int u2  = rem & 2047;
    int n   = u2 & 255;                           // n fastest -> coalesced
    int g   = u2 >> 8;                            // 16B group (0..7)
    const float* src = g_P + (size_t)(z + 1) * MAT + (size_t)(c * 64 + g * 8) * D + n;
    __half h[8], l[8];
#pragma unroll
    for (int e = 0; e < 8; ++e) {
        float v = src[(size_t)e * D] * 0.25f;
        __half hh = __float2half(v);
        h[e] = hh;
        l[e] = __float2half(v - __half2float(hh));
    }
    uint4 H, L;
    H.x = packh2(h[0], h[1]); H.y = packh2(h[2], h[3]);
    H.z = packh2(h[4], h[5]); H.w = packh2(h[6], h[7]);
    L.x = packh2(l[0], l[1]); L.y = packh2(l[2], l[3]);
    L.z = packh2(l[4], l[5]); L.w = packh2(l[6], l[7]);
    size_t base = ((size_t)(z * 4 + c) * 2) * 2048;
    int du = n * 8 + (g ^ (n & 7));
    g_PB[base + du]        = H;
    g_PB[base + 2048 + du] = L;
}

// A tiles: stored[m][k] = fp16(Z[m][k] * 2^-6), hi only
__global__ void convA_kernel() {
    int u = blockIdx.x * 256 + threadIdx.x;       // 0..262143
    int tile = u >> 12;
    int rem  = u & 4095;
    int c    = rem >> 10;
    int u2   = rem & 1023;
    int row  = u2 >> 3;
    int g    = u2 & 7;
    int m = tile * 128 + row;
    const float* src = g_Z + (size_t)m * D + c * 64 + g * 8;
    __half h[8];
#pragma unroll
    for (int e = 0; e < 8; ++e) h[e] = __float2half(src[e] * 0.015625f);
    uint4 H;
    H.x = packh2(h[0], h[1]); H.y = packh2(h[2], h[3]);
    H.z = packh2(h[4], h[5]); H.w = packh2(h[6], h[7]);
    size_t base = (size_t)(tile * 4 + c) * 1024;
    int du = row * 8 + (g ^ (row & 7));
    g_ZH[base + du] = H;
}

// ---------------------------------------------------------------------------
// HMMA fill: out[:, 128j+z, :] = Z_j @ P^(z+1), fp16 asymmetric 2-pass
// (A_hi * B_hi + A_hi * B_lo; epilogue x 256 undoes the 2^-8 operand scale).
// grid (128 tiles, 128 z), 256 threads, 2 CTAs/SM (96KB smem).
// Stage 48KB = A_hi 16K | B_hi 16K | B_lo 16K, double-buffered K-chunks of 64.
// 8 warps, warp tile 64x32, pass-major MMA issue (16-way ILP per pass).
// ---------------------------------------------------------------------------
#define STAGE_BYTES 49152
#define FILL_SMEM   (2 * STAGE_BYTES)   // 96 KB

__global__ __launch_bounds__(256, 2)
void fill_kernel(float* __restrict__ out) {
    extern __shared__ __align__(128) char sm[];
    const uint32_t sbase = smem_u32(sm);
    const int tid = threadIdx.x;
    const int tile_m = blockIdx.x >> 1, tile_n = blockIdx.x & 1;
    const int z = blockIdx.y;
    const int wid = tid >> 5, lid = tid & 31;
    const int warp_m = wid >> 2, warp_n = wid & 3;

    // stage: Ah [0,16K)  Bh [16K,32K)  Bl [32K,48K)
    auto issue = [&](int c, int buf) {
        const char* a0 = (const char*)(g_ZH + (size_t)(tile_m * 4 + c) * 1024)
                         + tid * 16;
        const char* b0 = (const char*)(g_PB + ((size_t)(z * 4 + c) * 2) * 2048
                                       + tile_n * 1024) + tid * 16;
        uint32_t d = sbase + buf * STAGE_BYTES + tid * 16;
#pragma unroll
        for (int q = 0; q < 4; ++q) {
            CP16(d + q * 4096,         a0 + q * 4096);            // Ah
            CP16(d + 16384 + q * 4096, b0 + q * 4096);            // Bh
            CP16(d + 32768 + q * 4096, b0 + 32768 + q * 4096);    // Bl
        }
        CP_COMMIT();
    };

    float acc[4][4][4];
#pragma unroll
    for (int i = 0; i < 4; ++i)
#pragma unroll
        for (int j = 0; j < 4; ++j)
#pragma unroll
            for (int q = 0; q < 4; ++q) acc[i][j][q] = 0.f;

    // ldmatrix addressing (rows base8-aligned => row&7 == lr)
    const int lq = lid >> 3, lr = lid & 7;
    const uint32_t a_row = warp_m * 64 + (lq & 1) * 8 + lr;
    const uint32_t b_row = warp_n * 32 + (lq & 1) * 8 + lr;
    const int gh = lq >> 1;

    issue(0, 0);
    for (int c = 0; c < 4; ++c) {
        if (c < 3) { issue(c + 1, (c + 1) & 1); CP_WAIT1(); }
        else       { CP_WAIT0(); }
        __syncthreads();

        const uint32_t ab  = sbase + (c & 1) * STAGE_BYTES;
        const uint32_t bhb = ab + 16384, blb = ab + 32768;
#pragma unroll
        for (int ks = 0; ks < 4; ++ks) {
            const uint32_t gx = ((uint32_t)(ks * 2 + gh) ^ lr) * 16;
            uint32_t ah[4][4], bh[2][4], bl[2][4];
#pragma unroll
            for (int mf = 0; mf < 4; ++mf)
                ldsm4(ah[mf], ab + (a_row + mf * 16) * 128 + gx);
#pragma unroll
            for (int nf = 0; nf < 2; ++nf) {
                ldsm4(bh[nf], bhb + (b_row + nf * 16) * 128 + gx);
                ldsm4(bl[nf], blb + (b_row + nf * 16) * 128 + gx);
            }
            // pass hh: 16 independent MMAs
#pragma unroll
            for (int mf = 0; mf < 4; ++mf)
#pragma unroll
                for (int j = 0; j < 4; ++j) {
                    const int n2 = j >> 1, e = j & 1;
                    mma16816h(acc[mf][j], ah[mf], bh[n2][e], bh[n2][e + 2]);
                }
            // pass hl: 16 independent MMAs
#pragma unroll
            for (int mf = 0; mf < 4; ++mf)
#pragma unroll
                for (int j = 0; j < 4; ++j) {
                    const int n2 = j >> 1, e = j & 1;
                    mma16816h(acc[mf][j], ah[mf], bl[n2][e], bl[n2][e + 2]);
                }
        }
        __syncthreads();
    }

    // epilogue: undo operand scaling (2^-6 * 2^-2 -> x256)
    const int t  = (tile_m >> 3) * CHUNK + z;
    const int b0 = (tile_m & 7) * 128 + warp_m * 64;
    const int nb = tile_n * 128 + warp_n * 32 + (lid & 3) * 2;
    const int rr = lid >> 2;
#pragma unroll
    for (int mf = 0; mf < 4; ++mf)
#pragma unroll
        for (int j = 0; j < 4; ++j) {
            int b = b0 + mf * 16 + rr;
            float* p0 = out + ((size_t)b * TSTEPS + t) * D + nb + j * 8;
            float* p1 = out + ((size_t)(b + 8) * TSTEPS + t) * D + nb + j * 8;
            *(float2*)p0 = make_float2(acc[mf][j][0] * 256.f, acc[mf][j][1] * 256.f);
            *(float2*)p1 = make_float2(acc[mf][j][2] * 256.f, acc[mf][j][3] * 256.f);
        }
}

// ---------------------------------------------------------------------------
// Launch sequence
// ---------------------------------------------------------------------------
extern "C" void kernel_launch(void* const* d_in, const int* in_sizes, int n_in,
                              void* d_out, int out_size) {
    const float* z0   = (const float*)d_in[0];
    const float* kern = (const float*)d_in[1];
    float* out = (float*)d_out;
    (void)in_sizes; (void)n_in; (void)out_size;

    // 1) A, P[1] = I + A, Z0 = z0
    prep_kernel<<<(BATCH * D) / 256, 256>>>(z0, kern);

    // 2) Taylor terms 2..5 (||A|| ~ 0.02 -> dropped term6 ~ 9e-14)
    int pp = 0;
    for (int k = 2; k <= 5; ++k) {
        gemm64_kernel<M_TAYLOR><<<dim3(4, 4), 128>>>(pp, 1.0f / (float)k);
        pp ^= 1;
    }

    // 3) Powers P[1..128] by batched doubling (fp32 exact chain)
    for (int m = 1; m < CHUNK; m <<= 1) {
        gemm64_kernel<M_PB><<<dim3(4, 4, m), 128>>>(m, 1.0f);
    }

    // 4) fp16 hi/lo tiling of all P powers (B operands, transposed, x 2^-2)
    convB_kernel<<<4096, 256>>>();

    // 5) Checkpoint chain Z[1..7] (fp32 exact)
    for (int j = 0; j < NJ - 1; ++j) {
        gemm64_kernel<M_PLAIN><<<dim3(4, 16), 128>>>(j, 1.0f);
    }

    // 6) fp16 hi tiling of checkpoints (A operands, x 2^-6)
    convA_kernel<<<1024, 256>>>();

    // 7) HMMA fill (fp16 2-pass, 2 CTAs/SM)
    cudaFuncSetAttribute(fill_kernel,
                         cudaFuncAttributeMaxDynamicSharedMemorySize, FILL_SMEM);
    dim3 gf(128, 128);
    fill_kernel<<<gf, 256, FILL_SMEM>>>(out);
}

// round 12
// speedup vs baseline: 3.0172x; 1.1256x over previous
#include <cuda_runtime.h>
#include <cuda_bf16.h>
#include <cuda_fp16.h>
#include <cstdint>

// Problem constants
#define D       256
#define BATCH   1024
#define TSTEPS  1024
#define CHUNK   128
#define NJ      (TSTEPS / CHUNK)   // 8 checkpoints
#define MAT     (D * D)
#define NCTA    512                // persistent preamble grid (guaranteed resident)

// ---------------------------------------------------------------------------
// Static device scratch
// ---------------------------------------------------------------------------
__device__ float g_A [MAT];
__device__ float g_T1[MAT];                   // taylor ping / later P256
__device__ float g_T2[MAT];                   // taylor pong / later P512
__device__ float g_X [4 * MAT];               // Q3, Q5, Q6, Q7 (E^384,640,768,896)
__device__ float g_P [(CHUNK + 1) * MAT];     // P[i] = E^i fp32, i=1..128
__device__ float g_Z [NJ * BATCH * D];        // fp32 checkpoints Z[j] = z0 E^{128j}
__device__ unsigned g_bar;                    // global barrier counter
// fp16 operands, pre-tiled + pre-swizzled (XOR-8 on 16B groups) for ldmatrix:
__device__ uint4 g_PB[128 * 4 * 2 * 2048];    // B^T tiles (hi/lo), 32 MB
__device__ uint4 g_ZH[64 * 4 * 1024];         // A tiles (hi only), 4 MB

// ---------------------------------------------------------------------------
// Helpers
// ---------------------------------------------------------------------------
__device__ __forceinline__ uint32_t smem_u32(const void* p) {
    uint32_t a;
    asm("{ .reg .u64 t; cvta.to.shared.u64 t, %1; cvt.u32.u64 %0, t; }"
        : "=r"(a) : "l"(p));
    return a;
}
__device__ __forceinline__ void fma2(unsigned long long& d,
                                     unsigned long long a,
                                     unsigned long long b) {
    asm("fma.rn.f32x2 %0, %1, %2, %0;" : "+l"(d) : "l"(a), "l"(b));
}
__device__ __forceinline__ unsigned long long dup2(float x) {
    unsigned long long r;
    asm("mov.b64 %0, {%1, %1};" : "=l"(r) : "f"(x));
    return r;
}
__device__ __forceinline__ void ldsm4(uint32_t* r, uint32_t addr) {
    asm volatile("ldmatrix.sync.aligned.m8n8.x4.shared.b16 {%0,%1,%2,%3}, [%4];"
                 : "=r"(r[0]), "=r"(r[1]), "=r"(r[2]), "=r"(r[3]) : "r"(addr));
}
__device__ __forceinline__ void mma16816h(float* d, const uint32_t* a,
                                          uint32_t b0, uint32_t b1) {
    asm volatile(
        "mma.sync.aligned.m16n8k16.row.col.f32.f16.f16.f32 "
        "{%0,%1,%2,%3}, {%4,%5,%6,%7}, {%8,%9}, {%0,%1,%2,%3};"
        : "+f"(d[0]), "+f"(d[1]), "+f"(d[2]), "+f"(d[3])
        : "r"(a[0]), "r"(a[1]), "r"(a[2]), "r"(a[3]), "r"(b0), "r"(b1));
}
#define CP16(dst, src) \
    asm volatile("cp.async.cg.shared.global [%0], [%1], 16;" \
                 :: "r"(dst), "l"(src))
#define CP_COMMIT() asm volatile("cp.async.commit_group;" ::: "memory")
#define CP_WAIT1()  asm volatile("cp.async.wait_group 1;" ::: "memory")
#define CP_WAIT0()  asm volatile("cp.async.wait_group 0;" ::: "memory")

// Global barrier (sense via monotonic counter; g_bar zeroed by prep each call).
// Spin reads bypass L1 (.cg); nanosleep keeps L2 pressure low.
__device__ __forceinline__ void gbar(unsigned& target) {
    __syncthreads();
    target += NCTA;
    if (threadIdx.x == 0) {
        __threadfence();
        atomicAdd(&g_bar, 1u);
        unsigned v;
        for (;;) {
            asm volatile("ld.global.cg.u32 %0, [%1];" : "=r"(v) : "l"(&g_bar));
            if (v >= target) break;
            __nanosleep(64);
        }
    }
    __syncthreads();
}

// ---------------------------------------------------------------------------
// prep: A = kernel*DT ; P[1] = I + A ; T1 = A ; Z[0] = z0 ; g_bar = 0
// ---------------------------------------------------------------------------
__global__ void prep_kernel(const float* __restrict__ z0,
                            const float* __restrict__ kern) {
    int idx = blockIdx.x * 256 + threadIdx.x;
    if (idx == 0) g_bar = 0;
    g_Z[idx] = z0[idx];
    if (idx < MAT) {
        float a = kern[idx] * 0.01f;
        g_A[idx]  = a;
        g_T1[idx] = a;
        int r = idx >> 8, c = idx & 255;
        g_P[MAT + idx] = a + (r == c ? 1.0f : 0.0f);
    }
}

// ---------------------------------------------------------------------------
// 64x64x256 FFMA2 tile GEMM (device fn, all-global-.cg for L1 coherence
// across the persistent kernel's barriers). 128 threads, 8x4 microtile.
// eacc: taylor mode — C = acc*scale and g_P[1] += acc*scale.
// ---------------------------------------------------------------------------
__device__ __forceinline__ void mm64(
    float (*As)[68], float (*Bs)[64],
    const float* A, const float* B, float* C,
    int bM, int bN, float scale, bool eacc)
{
    const int tid = threadIdx.x;
    const int tx = tid & 15, ty = tid >> 4;

    unsigned long long acc[8][2];
#pragma unroll
    for (int i = 0; i < 8; ++i) { acc[i][0] = 0ull; acc[i][1] = 0ull; }

    const int a_r = tid >> 1, a_k = (tid & 1) * 8;
    const int b_k = tid >> 3, b_n = (tid & 7) * 8;

    const float* Ap = A + (size_t)(bM * 64 + a_r) * D + a_k;
    const float* Bp = B + (size_t)b_k * D + bN * 64 + b_n;

    float4 pa0 = __ldcg((const float4*)Ap);
    float4 pa1 = __ldcg((const float4*)(Ap + 4));
    float4 pb0 = __ldcg((const float4*)Bp);
    float4 pb1 = __ldcg((const float4*)(Bp + 4));

    for (int kt = 0; kt < 16; ++kt) {
        As[a_k + 0][a_r] = pa0.x; As[a_k + 1][a_r] = pa0.y;
        As[a_k + 2][a_r] = pa0.z; As[a_k + 3][a_r] = pa0.w;
        As[a_k + 4][a_r] = pa1.x; As[a_k + 5][a_r] = pa1.y;
        As[a_k + 6][a_r] = pa1.z; As[a_k + 7][a_r] = pa1.w;
        *(float4*)&Bs[b_k][b_n]     = pb0;
        *(float4*)&Bs[b_k][b_n + 4] = pb1;
        __syncthreads();

        if (kt < 15) {
            pa0 = __ldcg((const float4*)(Ap + (kt + 1) * 16));
            pa1 = __ldcg((const float4*)(Ap + (kt + 1) * 16 + 4));
            pb0 = __ldcg((const float4*)(Bp + (size_t)(kt + 1) * 16 * D));
            pb1 = __ldcg((const float4*)(Bp + (size_t)(kt + 1) * 16 * D + 4));
        }

#pragma unroll
        for (int kk = 0; kk < 16; ++kk) {
            float4 a0 = *(const float4*)&As[kk][ty * 8];
            float4 a1 = *(const float4*)&As[kk][ty * 8 + 4];
            ulonglong2 bq = *(const ulonglong2*)&Bs[kk][tx * 4];
            float a[8] = {a0.x, a0.y, a0.z, a0.w, a1.x, a1.y, a1.z, a1.w};
#pragma unroll
            for (int i = 0; i < 8; ++i) {
                unsigned long long aa = dup2(a[i]);
                fma2(acc[i][0], aa, bq.x);
                fma2(acc[i][1], aa, bq.y);
            }
        }
        __syncthreads();
    }

#pragma unroll
    for (int i = 0; i < 8; ++i) {
        int row = bM * 64 + ty * 8 + i;
        int col = bN * 64 + tx * 4;
        size_t idx = (size_t)row * D + col;
        if (eacc) {
            ulonglong2 v; v.x = acc[i][0]; v.y = acc[i][1];
            float* fv = (float*)&v;
#pragma unroll
            for (int j = 0; j < 4; ++j) {
                float s = fv[j] * scale;
                C[idx + j] = s;
                g_P[MAT + idx + j] = __ldcg(g_P + MAT + idx + j) + s;
            }
        } else {
            ulonglong2 v; v.x = acc[i][0]; v.y = acc[i][1];
            *(ulonglong2*)(C + idx) = v;
        }
    }
}

// ---------------------------------------------------------------------------
// conv item helpers (fp16 split + pre-tile + XOR-8 pre-swizzle)
// ---------------------------------------------------------------------------
__device__ __forceinline__ uint32_t packh2(__half a, __half b) {
    __half_raw ar = *(__half_raw*)&a, br = *(__half_raw*)&b;
    return (uint32_t)ar.x | ((uint32_t)br.x << 16);
}

__device__ __forceinline__ void convB_item(int u) {
    int z   = u >> 13;
    int rem = u & 8191;
    int c   = rem >> 11;
    int u2  = rem & 2047;
    int n   = u2 & 255;
    int g   = u2 >> 8;
    const float* src = g_P + (size_t)(z + 1) * MAT + (size_t)(c * 64 + g * 8) * D + n;
    __half h[8], l[8];
#pragma unroll
    for (int e = 0; e < 8; ++e) {
        float v = __ldcg(src + (size_t)e * D) * 0.25f;
        __half hh = __float2half(v);
        h[e] = hh;
        l[e] = __float2half(v - __half2float(hh));
    }
    uint4 H, L;
    H.x = packh2(h[0], h[1]); H.y = packh2(h[2], h[3]);
    H.z = packh2(h[4], h[5]); H.w = packh2(h[6], h[7]);
    L.x = packh2(l[0], l[1]); L.y = packh2(l[2], l[3]);
    L.z = packh2(l[4], l[5]); L.w = packh2(l[6], l[7]);
    size_t base = ((size_t)(z * 4 + c) * 2) * 2048;
    int du = n * 8 + (g ^ (n & 7));
    g_PB[base + du]        = H;
    g_PB[base + 2048 + du] = L;
}

__device__ __forceinline__ void convA_item(int u) {
    int tile = u >> 12;
    int rem  = u & 4095;
    int c    = rem >> 10;
    int u2   = rem & 1023;
    int row  = u2 >> 3;
    int g    = u2 & 7;
    int m = tile * 128 + row;
    const float* src = g_Z + (size_t)m * D + c * 64 + g * 8;
    __half h[8];
#pragma unroll
    for (int e = 0; e < 8; ++e) h[e] = __float2half(__ldcg(src + e) * 0.015625f);
    uint4 H;
    H.x = packh2(h[0], h[1]); H.y = packh2(h[2], h[3]);
    H.z = packh2(h[4], h[5]); H.w = packh2(h[6], h[7]);
    size_t base = (size_t)(tile * 4 + c) * 1024;
    int du = row * 8 + (g ^ (row & 7));
    g_ZH[base + du] = H;
}

// ---------------------------------------------------------------------------
// Persistent preamble: taylor(4) -> doubling(7) -> P256,P512 -> Q batches(2)
// -> Z (parallel, 7 independent GEMMs) -> convA + convB. 16 global barriers.
// 512 CTAs x 128 thr, launch_bounds(128,4) guarantees residency (592 slots).
// ---------------------------------------------------------------------------
__global__ __launch_bounds__(128, 4)
void preamble_kernel() {
    __shared__ float As[16][68];
    __shared__ float Bs[16][64];
    const int cta = blockIdx.x;
    unsigned target = 0;

    // Taylor terms k=2..5: Tout = (Tin @ A)/k ; E += Tout
    for (int s = 0; s < 4; ++s) {
        const float* Tin  = (s & 1) ? g_T2 : g_T1;
        float*       Tout = (s & 1) ? g_T1 : g_T2;
        float inv = 1.0f / (float)(s + 2);
        for (int j = cta; j < 16; j += NCTA)
            mm64(As, Bs, Tin, g_A, Tout, j >> 2, j & 3, inv, true);
        gbar(target);
    }

    // Powers P[2..128] by batched doubling: P[m+i] = P[m] @ P[i], i=1..m
    for (int m = 1; m <= 64; m <<= 1) {
        int njobs = 16 * m;
        for (int j = cta; j < njobs; j += NCTA) {
            int i = 1 + (j >> 4), t = j & 15;
            mm64(As, Bs, g_P + (size_t)m * MAT, g_P + (size_t)i * MAT,
                 g_P + (size_t)(m + i) * MAT, t >> 2, t & 3, 1.f, false);
        }
        gbar(target);
    }

    // P256 = P128^2 -> T1
    for (int j = cta; j < 16; j += NCTA)
        mm64(As, Bs, g_P + (size_t)128 * MAT, g_P + (size_t)128 * MAT, g_T1,
             j >> 2, j & 3, 1.f, false);
    gbar(target);
    // P512 = P256^2 -> T2
    for (int j = cta; j < 16; j += NCTA)
        mm64(As, Bs, g_T1, g_T1, g_T2, j >> 2, j & 3, 1.f, false);
    gbar(target);

    // Q batch 1: X0 = E^384 = P128@P256, X1 = E^640 = P128@P512, X2 = E^768 = P256@P512
    for (int j = cta; j < 48; j += NCTA) {
        int q = j >> 4, t = j & 15;
        const float* Aq = (q == 2) ? g_T1 : g_P + (size_t)128 * MAT;
        const float* Bq = (q == 0) ? g_T1 : g_T2;
        mm64(As, Bs, Aq, Bq, g_X + (size_t)q * MAT, t >> 2, t & 3, 1.f, false);
    }
    gbar(target);
    // Q batch 2: X3 = E^896 = X0 @ P512
    for (int j = cta; j < 16; j += NCTA)
        mm64(As, Bs, g_X, g_T2, g_X + (size_t)3 * MAT, j >> 2, j & 3, 1.f, false);
    gbar(target);

    // Z stage (fully parallel): Z[j] = z0 @ Q_j, j=1..7 -> 448 tile jobs
    for (int j = cta; j < 448; j += NCTA) {
        int zj = 1 + (j >> 6), t = j & 63;
        const float* Q =
            (zj == 1) ? g_P + (size_t)128 * MAT :
            (zj == 2) ? g_T1 :
            (zj == 3) ? g_X :
            (zj == 4) ? g_T2 :
            (zj == 5) ? g_X + (size_t)1 * MAT :
            (zj == 6) ? g_X + (size_t)2 * MAT : g_X + (size_t)3 * MAT;
        mm64(As, Bs, g_Z, Q, g_Z + (size_t)zj * (BATCH * D),
             t >> 2, t & 3, 1.f, false);
    }
    gbar(target);

    // conv stages (65536 threads total)
    int gt = cta * 128 + threadIdx.x;
#pragma unroll
    for (int r = 0; r < 4; ++r) convA_item(gt + r * 65536);
#pragma unroll
    for (int r = 0; r < 16; ++r) convB_item(gt + r * 65536);
}

// ---------------------------------------------------------------------------
// HMMA fill (unchanged from R11, known-good): fp16 asymmetric 2-pass,
// 2 CTAs/SM, double-buffered cp.async, warp tile 64x32, pass-major issue.
// ---------------------------------------------------------------------------
#define STAGE_BYTES 49152
#define FILL_SMEM   (2 * STAGE_BYTES)   // 96 KB

__global__ __launch_bounds__(256, 2)
void fill_kernel(float* __restrict__ out) {
    extern __shared__ __align__(128) char sm[];
    const uint32_t sbase = smem_u32(sm);
    const int tid = threadIdx.x;
    const int tile_m = blockIdx.x >> 1, tile_n = blockIdx.x & 1;
    const int z = blockIdx.y;
    const int wid = tid >> 5, lid = tid & 31;
    const int warp_m = wid >> 2, warp_n = wid & 3;

    auto issue = [&](int c, int buf) {
        const char* a0 = (const char*)(g_ZH + (size_t)(tile_m * 4 + c) * 1024)
                         + tid * 16;
        const char* b0 = (const char*)(g_PB + ((size_t)(z * 4 + c) * 2) * 2048
                                       + tile_n * 1024) + tid * 16;
        uint32_t d = sbase + buf * STAGE_BYTES + tid * 16;
#pragma unroll
        for (int q = 0; q < 4; ++q) {
            CP16(d + q * 4096,         a0 + q * 4096);            // Ah
            CP16(d + 16384 + q * 4096, b0 + q * 4096);            // Bh
            CP16(d + 32768 + q * 4096, b0 + 32768 + q * 4096);    // Bl
        }
        CP_COMMIT();
    };

    float acc[4][4][4];
#pragma unroll
    for (int i = 0; i < 4; ++i)
#pragma unroll
        for (int j = 0; j < 4; ++j)
#pragma unroll
            for (int q = 0; q < 4; ++q) acc[i][j][q] = 0.f;

    const int lq = lid >> 3, lr = lid & 7;
    const uint32_t a_row = warp_m * 64 + (lq & 1) * 8 + lr;
    const uint32_t b_row = warp_n * 32 + (lq & 1) * 8 + lr;
    const int gh = lq >> 1;

    issue(0, 0);
    for (int c = 0; c < 4; ++c) {
        if (c < 3) { issue(c + 1, (c + 1) & 1); CP_WAIT1(); }
        else       { CP_WAIT0(); }
        __syncthreads();

        const uint32_t ab  = sbase + (c & 1) * STAGE_BYTES;
        const uint32_t bhb = ab + 16384, blb = ab + 32768;
#pragma unroll
        for (int ks = 0; ks < 4; ++ks) {
            const uint32_t gx = ((uint32_t)(ks * 2 + gh) ^ lr) * 16;
            uint32_t ah[4][4], bh[2][4], bl[2][4];
#pragma unroll
            for (int mf = 0; mf < 4; ++mf)
                ldsm4(ah[mf], ab + (a_row + mf * 16) * 128 + gx);
#pragma unroll
            for (int nf = 0; nf < 2; ++nf) {
                ldsm4(bh[nf], bhb + (b_row + nf * 16) * 128 + gx);
                ldsm4(bl[nf], blb + (b_row + nf * 16) * 128 + gx);
            }
#pragma unroll
            for (int mf = 0; mf < 4; ++mf)
#pragma unroll
                for (int j = 0; j < 4; ++j) {
                    const int n2 = j >> 1, e = j & 1;
                    mma16816h(acc[mf][j], ah[mf], bh[n2][e], bh[n2][e + 2]);
                }
#pragma unroll
            for (int mf = 0; mf < 4; ++mf)
#pragma unroll
                for (int j = 0; j < 4; ++j) {
                    const int n2 = j >> 1, e = j & 1;
                    mma16816h(acc[mf][j], ah[mf], bl[n2][e], bl[n2][e + 2]);
                }
        }
        __syncthreads();
    }

    const int t  = (tile_m >> 3) * CHUNK + z;
    const int b0 = (tile_m & 7) * 128 + warp_m * 64;
    const int nb = tile_n * 128 + warp_n * 32 + (lid & 3) * 2;
    const int rr = lid >> 2;
#pragma unroll
    for (int mf = 0; mf < 4; ++mf)
#pragma unroll
        for (int j = 0; j < 4; ++j) {
            int b = b0 + mf * 16 + rr;
            float* p0 = out + ((size_t)b * TSTEPS + t) * D + nb + j * 8;
            float* p1 = out + ((size_t)(b + 8) * TSTEPS + t) * D + nb + j * 8;
            *(float2*)p0 = make_float2(acc[mf][j][0] * 256.f, acc[mf][j][1] * 256.f);
            *(float2*)p1 = make_float2(acc[mf][j][2] * 256.f, acc[mf][j][3] * 256.f);
        }
}

// ---------------------------------------------------------------------------
// Launch sequence: prep -> persistent preamble -> fill
// ---------------------------------------------------------------------------
extern "C" void kernel_launch(void* const* d_in, const int* in_sizes, int n_in,
                              void* d_out, int out_size) {
    const float* z0   = (const float*)d_in[0];
    const float* kern = (const float*)d_in[1];
    float* out = (float*)d_out;
    (void)in_sizes; (void)n_in; (void)out_size;

    prep_kernel<<<(BATCH * D) / 256, 256>>>(z0, kern);

    preamble_kernel<<<NCTA, 128>>>();

    cudaFuncSetAttribute(fill_kernel,
                         cudaFuncAttributeMaxDynamicSharedMemorySize, FILL_SMEM);
    dim3 gf(128, 128);
    fill_kernel<<<gf, 256, FILL_SMEM>>>(out);
}

// round 13
// speedup vs baseline: 4.0417x; 1.3396x over previous
#include <cuda_runtime.h>
#include <cuda_bf16.h>
#include <cuda_fp16.h>
#include <cstdint>

// Problem constants
#define D       256
#define BATCH   1024
#define TSTEPS  1024
#define CHUNK   128
#define NJ      (TSTEPS / CHUNK)   // 8 checkpoints
#define MAT     (D * D)
#define NCTA    512                // persistent preamble grid (guaranteed resident)

// ---------------------------------------------------------------------------
// Static device scratch
// ---------------------------------------------------------------------------
__device__ float g_A [MAT];
__device__ float g_T1[MAT];                   // taylor ping / later P256
__device__ float g_T2[MAT];                   // taylor pong / later P512
__device__ float g_X [4 * MAT];               // E^384, E^640, E^768, E^896
__device__ float g_P [(CHUNK + 1) * MAT];     // P[i] = E^i fp32, i=1..128
__device__ float g_Z [NJ * BATCH * D];        // fp32 checkpoints Z[j] = z0 E^{128j}
__device__ unsigned g_bar;                    // global barrier counter
// fp16 operands, pre-tiled + pre-swizzled (XOR-8 on 16B groups) for ldmatrix:
__device__ uint4 g_PB[128 * 4 * 2048];        // B^T tiles (hi only), 16 MB
__device__ uint4 g_ZH[64 * 4 * 1024];         // A tiles (hi only), 4 MB

// ---------------------------------------------------------------------------
// Helpers
// ---------------------------------------------------------------------------
__device__ __forceinline__ uint32_t smem_u32(const void* p) {
    uint32_t a;
    asm("{ .reg .u64 t; cvta.to.shared.u64 t, %1; cvt.u32.u64 %0, t; }"
        : "=r"(a) : "l"(p));
    return a;
}
__device__ __forceinline__ void fma2(unsigned long long& d,
                                     unsigned long long a,
                                     unsigned long long b) {
    asm("fma.rn.f32x2 %0, %1, %2, %0;" : "+l"(d) : "l"(a), "l"(b));
}
__device__ __forceinline__ unsigned long long dup2(float x) {
    unsigned long long r;
    asm("mov.b64 %0, {%1, %1};" : "=l"(r) : "f"(x));
    return r;
}
__device__ __forceinline__ void ldsm4(uint32_t* r, uint32_t addr) {
    asm volatile("ldmatrix.sync.aligned.m8n8.x4.shared.b16 {%0,%1,%2,%3}, [%4];"
                 : "=r"(r[0]), "=r"(r[1]), "=r"(r[2]), "=r"(r[3]) : "r"(addr));
}
__device__ __forceinline__ void mma16816h(float* d, const uint32_t* a,
                                          uint32_t b0, uint32_t b1) {
    asm volatile(
        "mma.sync.aligned.m16n8k16.row.col.f32.f16.f16.f32 "
        "{%0,%1,%2,%3}, {%4,%5,%6,%7}, {%8,%9}, {%0,%1,%2,%3};"
        : "+f"(d[0]), "+f"(d[1]), "+f"(d[2]), "+f"(d[3])
        : "r"(a[0]), "r"(a[1]), "r"(a[2]), "r"(a[3]), "r"(b0), "r"(b1));
}
#define CP16(dst, src) \
    asm volatile("cp.async.cg.shared.global [%0], [%1], 16;" \
                 :: "r"(dst), "l"(src))
#define CP_COMMIT() asm volatile("cp.async.commit_group;" ::: "memory")
#define CP_WAIT1()  asm volatile("cp.async.wait_group 1;" ::: "memory")
#define CP_WAIT0()  asm volatile("cp.async.wait_group 0;" ::: "memory")

// Global barrier (monotonic counter; zeroed by prep each call).
__device__ __forceinline__ void gbar(unsigned& target) {
    __syncthreads();
    target += NCTA;
    if (threadIdx.x == 0) {
        __threadfence();
        atomicAdd(&g_bar, 1u);
        unsigned v;
        for (;;) {
            asm volatile("ld.global.cg.u32 %0, [%1];" : "=r"(v) : "l"(&g_bar));
            if (v >= target) break;
            __nanosleep(64);
        }
    }
    __syncthreads();
}

// ---------------------------------------------------------------------------
// prep: A = kernel*DT ; P[1] = I + A ; T1 = A ; Z[0] = z0 ; g_bar = 0
// ---------------------------------------------------------------------------
__global__ void prep_kernel(const float* __restrict__ z0,
                            const float* __restrict__ kern) {
    int idx = blockIdx.x * 256 + threadIdx.x;
    if (idx == 0) g_bar = 0;
    g_Z[idx] = z0[idx];
    if (idx < MAT) {
        float a = kern[idx] * 0.01f;
        g_A[idx]  = a;
        g_T1[idx] = a;
        int r = idx >> 8, c = idx & 255;
        g_P[MAT + idx] = a + (r == c ? 1.0f : 0.0f);
    }
}

// ---------------------------------------------------------------------------
// 64x64x256 FFMA2 tile GEMM (device fn; .cg global loads for coherence
// across the persistent kernel's barriers). 128 threads, 8x4 microtile.
// ---------------------------------------------------------------------------
__device__ __forceinline__ void mm64(
    float (*As)[68], float (*Bs)[64],
    const float* A, const float* B, float* C,
    int bM, int bN, float scale, bool eacc)
{
    const int tid = threadIdx.x;
    const int tx = tid & 15, ty = tid >> 4;

    unsigned long long acc[8][2];
#pragma unroll
    for (int i = 0; i < 8; ++i) { acc[i][0] = 0ull; acc[i][1] = 0ull; }

    const int a_r = tid >> 1, a_k = (tid & 1) * 8;
    const int b_k = tid >> 3, b_n = (tid & 7) * 8;

    const float* Ap = A + (size_t)(bM * 64 + a_r) * D + a_k;
    const float* Bp = B + (size_t)b_k * D + bN * 64 + b_n;

    float4 pa0 = __ldcg((const float4*)Ap);
    float4 pa1 = __ldcg((const float4*)(Ap + 4));
    float4 pb0 = __ldcg((const float4*)Bp);
    float4 pb1 = __ldcg((const float4*)(Bp + 4));

    for (int kt = 0; kt < 16; ++kt) {
        As[a_k + 0][a_r] = pa0.x; As[a_k + 1][a_r] = pa0.y;
        As[a_k + 2][a_r] = pa0.z; As[a_k + 3][a_r] = pa0.w;
        As[a_k + 4][a_r] = pa1.x; As[a_k + 5][a_r] = pa1.y;
        As[a_k + 6][a_r] = pa1.z; As[a_k + 7][a_r] = pa1.w;
        *(float4*)&Bs[b_k][b_n]     = pb0;
        *(float4*)&Bs[b_k][b_n + 4] = pb1;
        __syncthreads();

        if (kt < 15) {
            pa0 = __ldcg((const float4*)(Ap + (kt + 1) * 16));
            pa1 = __ldcg((const float4*)(Ap + (kt + 1) * 16 + 4));
            pb0 = __ldcg((const float4*)(Bp + (size_t)(kt + 1) * 16 * D));
            pb1 = __ldcg((const float4*)(Bp + (size_t)(kt + 1) * 16 * D + 4));
        }

#pragma unroll
        for (int kk = 0; kk < 16; ++kk) {
            float4 a0 = *(const float4*)&As[kk][ty * 8];
            float4 a1 = *(const float4*)&As[kk][ty * 8 + 4];
            ulonglong2 bq = *(const ulonglong2*)&Bs[kk][tx * 4];
            float a[8] = {a0.x, a0.y, a0.z, a0.w, a1.x, a1.y, a1.z, a1.w};
#pragma unroll
            for (int i = 0; i < 8; ++i) {
                unsigned long long aa = dup2(a[i]);
                fma2(acc[i][0], aa, bq.x);
                fma2(acc[i][1], aa, bq.y);
            }
        }
        __syncthreads();
    }

#pragma unroll
    for (int i = 0; i < 8; ++i) {
        int row = bM * 64 + ty * 8 + i;
        int col = bN * 64 + tx * 4;
        size_t idx = (size_t)row * D + col;
        if (eacc) {
            ulonglong2 v; v.x = acc[i][0]; v.y = acc[i][1];
            float* fv = (float*)&v;
#pragma unroll
            for (int j = 0; j < 4; ++j) {
                float s = fv[j] * scale;
                C[idx + j] = s;
                g_P[MAT + idx + j] = __ldcg(g_P + MAT + idx + j) + s;
            }
        } else {
            ulonglong2 v; v.x = acc[i][0]; v.y = acc[i][1];
            *(ulonglong2*)(C + idx) = v;
        }
    }
}

// ---------------------------------------------------------------------------
// conv items (fp16 quantize + pre-tile + XOR-8 pre-swizzle)
// ---------------------------------------------------------------------------
__device__ __forceinline__ uint32_t packh2(__half a, __half b) {
    __half_raw ar = *(__half_raw*)&a, br = *(__half_raw*)&b;
    return (uint32_t)ar.x | ((uint32_t)br.x << 16);
}

// B tiles: stored[n][k] = fp16(P^(z+1)[k][n] * 2^-2), hi only
__device__ __forceinline__ void convB_item(int u) {
    int z   = u >> 13;
    int rem = u & 8191;
    int c   = rem >> 11;
    int u2  = rem & 2047;
    int n   = u2 & 255;
    int g   = u2 >> 8;
    const float* src = g_P + (size_t)(z + 1) * MAT + (size_t)(c * 64 + g * 8) * D + n;
    __half h[8];
#pragma unroll
    for (int e = 0; e < 8; ++e)
        h[e] = __float2half(__ldcg(src + (size_t)e * D) * 0.25f);
    uint4 H;
    H.x = packh2(h[0], h[1]); H.y = packh2(h[2], h[3]);
    H.z = packh2(h[4], h[5]); H.w = packh2(h[6], h[7]);
    size_t base = (size_t)(z * 4 + c) * 2048;
    int du = n * 8 + (g ^ (n & 7));
    g_PB[base + du] = H;
}

// A tiles: stored[m][k] = fp16(Z[m][k] * 2^-6)
__device__ __forceinline__ void convA_item(int u) {
    int tile = u >> 12;
    int rem  = u & 4095;
    int c    = rem >> 10;
    int u2   = rem & 1023;
    int row  = u2 >> 3;
    int g    = u2 & 7;
    int m = tile * 128 + row;
    const float* src = g_Z + (size_t)m * D + c * 64 + g * 8;
    __half h[8];
#pragma unroll
    for (int e = 0; e < 8; ++e) h[e] = __float2half(__ldcg(src + e) * 0.015625f);
    uint4 H;
    H.x = packh2(h[0], h[1]); H.y = packh2(h[2], h[3]);
    H.z = packh2(h[4], h[5]); H.w = packh2(h[6], h[7]);
    size_t base = (size_t)(tile * 4 + c) * 1024;
    int du = row * 8 + (g ^ (row & 7));
    g_ZH[base + du] = H;
}

// ---------------------------------------------------------------------------
// Persistent preamble: taylor(4) -> doubling(7) -> P256,P512 -> Q(2)
// -> Z (parallel) -> convA + convB. 16 global barriers.
// ---------------------------------------------------------------------------
__global__ __launch_bounds__(128, 4)
void preamble_kernel() {
    __shared__ float As[16][68];
    __shared__ float Bs[16][64];
    const int cta = blockIdx.x;
    unsigned target = 0;

    // Taylor terms k=2..5
    for (int s = 0; s < 4; ++s) {
        const float* Tin  = (s & 1) ? g_T2 : g_T1;
        float*       Tout = (s & 1) ? g_T1 : g_T2;
        float inv = 1.0f / (float)(s + 2);
        for (int j = cta; j < 16; j += NCTA)
            mm64(As, Bs, Tin, g_A, Tout, j >> 2, j & 3, inv, true);
        gbar(target);
    }

    // Powers P[2..128] by batched doubling
    for (int m = 1; m <= 64; m <<= 1) {
        int njobs = 16 * m;
        for (int j = cta; j < njobs; j += NCTA) {
            int i = 1 + (j >> 4), t = j & 15;
            mm64(As, Bs, g_P + (size_t)m * MAT, g_P + (size_t)i * MAT,
                 g_P + (size_t)(m + i) * MAT, t >> 2, t & 3, 1.f, false);
        }
        gbar(target);
    }

    // P256 -> T1 ; P512 -> T2
    for (int j = cta; j < 16; j += NCTA)
        mm64(As, Bs, g_P + (size_t)128 * MAT, g_P + (size_t)128 * MAT, g_T1,
             j >> 2, j & 3, 1.f, false);
    gbar(target);
    for (int j = cta; j < 16; j += NCTA)
        mm64(As, Bs, g_T1, g_T1, g_T2, j >> 2, j & 3, 1.f, false);
    gbar(target);

    // Q batch 1: X0=E^384, X1=E^640, X2=E^768
    for (int j = cta; j < 48; j += NCTA) {
        int q = j >> 4, t = j & 15;
        const float* Aq = (q == 2) ? g_T1 : g_P + (size_t)128 * MAT;
        const float* Bq = (q == 0) ? g_T1 : g_T2;
        mm64(As, Bs, Aq, Bq, g_X + (size_t)q * MAT, t >> 2, t & 3, 1.f, false);
    }
    gbar(target);
    // Q batch 2: X3 = E^896
    for (int j = cta; j < 16; j += NCTA)
        mm64(As, Bs, g_X, g_T2, g_X + (size_t)3 * MAT, j >> 2, j & 3, 1.f, false);
    gbar(target);

    // Z stage (fully parallel): Z[j] = z0 @ Q_j, j=1..7
    for (int j = cta; j < 448; j += NCTA) {
        int zj = 1 + (j >> 6), t = j & 63;
        const float* Q =
            (zj == 1) ? g_P + (size_t)128 * MAT :
            (zj == 2) ? g_T1 :
            (zj == 3) ? g_X :
            (zj == 4) ? g_T2 :
            (zj == 5) ? g_X + (size_t)1 * MAT :
            (zj == 6) ? g_X + (size_t)2 * MAT : g_X + (size_t)3 * MAT;
        mm64(As, Bs, g_Z, Q, g_Z + (size_t)zj * (BATCH * D),
             t >> 2, t & 3, 1.f, false);
    }
    gbar(target);

    // conv stages
    int gt = cta * 128 + threadIdx.x;
#pragma unroll
    for (int r = 0; r < 4; ++r) convA_item(gt + r * 65536);
#pragma unroll
    for (int r = 0; r < 16; ++r) convB_item(gt + r * 65536);
}

// ---------------------------------------------------------------------------
// HMMA fill: out[:, 128j+z, :] = Z_j @ P^(z+1), SINGLE-pass fp16
// (A_hi * B_hi; epilogue x 256 undoes 2^-6 * 2^-2 operand scaling).
// grid (128 tiles, 128 z), 256 threads, 2 CTAs/SM.
// Stage 32KB = A_hi 16K | B_hi 16K, double-buffered K-chunks of 64.
// ---------------------------------------------------------------------------
#define STAGE_BYTES 32768
#define FILL_SMEM   (2 * STAGE_BYTES)   // 64 KB

__global__ __launch_bounds__(256, 2)
void fill_kernel(float* __restrict__ out) {
    extern __shared__ __align__(128) char sm[];
    const uint32_t sbase = smem_u32(sm);
    const int tid = threadIdx.x;
    const int tile_m = blockIdx.x >> 1, tile_n = blockIdx.x & 1;
    const int z = blockIdx.y;
    const int wid = tid >> 5, lid = tid & 31;
    const int warp_m = wid >> 2, warp_n = wid & 3;

    // stage: Ah [0,16K)  Bh [16K,32K)
    auto issue = [&](int c, int buf) {
        const char* a0 = (const char*)(g_ZH + (size_t)(tile_m * 4 + c) * 1024)
                         + tid * 16;
        const char* b0 = (const char*)(g_PB + (size_t)(z * 4 + c) * 2048
                                       + tile_n * 1024) + tid * 16;
        uint32_t d = sbase + buf * STAGE_BYTES + tid * 16;
#pragma unroll
        for (int q = 0; q < 4; ++q) {
            CP16(d + q * 4096,         a0 + q * 4096);            // Ah
            CP16(d + 16384 + q * 4096, b0 + q * 4096);            // Bh
        }
        CP_COMMIT();
    };

    float acc[4][4][4];
#pragma unroll
    for (int i = 0; i < 4; ++i)
#pragma unroll
        for (int j = 0; j < 4; ++j)
#pragma unroll
            for (int q = 0; q < 4; ++q) acc[i][j][q] = 0.f;

    const int lq = lid >> 3, lr = lid & 7;
    const uint32_t a_row = warp_m * 64 + (lq & 1) * 8 + lr;
    const uint32_t b_row = warp_n * 32 + (lq & 1) * 8 + lr;
    const int gh = lq >> 1;

    issue(0, 0);
    for (int c = 0; c < 4; ++c) {
        if (c < 3) { issue(c + 1, (c + 1) & 1); CP_WAIT1(); }
        else       { CP_WAIT0(); }
        __syncthreads();

        const uint32_t ab  = sbase + (c & 1) * STAGE_BYTES;
        const uint32_t bhb = ab + 16384;
#pragma unroll
        for (int ks = 0; ks < 4; ++ks) {
            const uint32_t gx = ((uint32_t)(ks * 2 + gh) ^ lr) * 16;
            uint32_t ah[4][4], bh[2][4];
#pragma unroll
            for (int mf = 0; mf < 4; ++mf)
                ldsm4(ah[mf], ab + (a_row + mf * 16) * 128 + gx);
#pragma unroll
            for (int nf = 0; nf < 2; ++nf)
                ldsm4(bh[nf], bhb + (b_row + nf * 16) * 128 + gx);
#pragma unroll
            for (int mf = 0; mf < 4; ++mf)
#pragma unroll
                for (int j = 0; j < 4; ++j) {
                    const int n2 = j >> 1, e = j & 1;
                    mma16816h(acc[mf][j], ah[mf], bh[n2][e], bh[n2][e + 2]);
                }
        }
        __syncthreads();
    }

    // epilogue: undo operand scaling (2^-6 * 2^-2 -> x256)
    const int t  = (tile_m >> 3) * CHUNK + z;
    const int b0 = (tile_m & 7) * 128 + warp_m * 64;
    const int nb = tile_n * 128 + warp_n * 32 + (lid & 3) * 2;
    const int rr = lid >> 2;
#pragma unroll
    for (int mf = 0; mf < 4; ++mf)
#pragma unroll
        for (int j = 0; j < 4; ++j) {
            int b = b0 + mf * 16 + rr;
            float* p0 = out + ((size_t)b * TSTEPS + t) * D + nb + j * 8;
            float* p1 = out + ((size_t)(b + 8) * TSTEPS + t) * D + nb + j * 8;
            *(float2*)p0 = make_float2(acc[mf][j][0] * 256.f, acc[mf][j][1] * 256.f);
            *(float2*)p1 = make_float2(acc[mf][j][2] * 256.f, acc[mf][j][3] * 256.f);
        }
}

// ---------------------------------------------------------------------------
// Launch sequence: prep -> persistent preamble -> fill
// ---------------------------------------------------------------------------
extern "C" void kernel_launch(void* const* d_in, const int* in_sizes, int n_in,
                              void* d_out, int out_size) {
    const float* z0   = (const float*)d_in[0];
    const float* kern = (const float*)d_in[1];
    float* out = (float*)d_out;
    (void)in_sizes; (void)n_in; (void)out_size;

    prep_kernel<<<(BATCH * D) / 256, 256>>>(z0, kern);

    preamble_kernel<<<NCTA, 128>>>();

    cudaFuncSetAttribute(fill_kernel,
                         cudaFuncAttributeMaxDynamicSharedMemorySize, FILL_SMEM);
    dim3 gf(128, 128);
    fill_kernel<<<gf, 256, FILL_SMEM>>>(out);
}

// round 14
// speedup vs baseline: 4.3690x; 1.0810x over previous
#include <cuda_runtime.h>
#include <cuda_fp16.h>
#include <cstdint>

// Problem constants
#define D       256
#define BATCH   1024
#define TSTEPS  1024
#define CHUNK   128
#define MAT     (D * D)
#define NCTA    512                // persistent preamble grid (guaranteed resident)

// ---------------------------------------------------------------------------
// Static device scratch
// ---------------------------------------------------------------------------
__device__ float g_A [MAT];                   // A = kernel * DT
__device__ float g_T1[MAT];                   // D2, later P512
__device__ float g_T2[MAT];                   // D1, later P256
__device__ float g_X [4 * MAT];               // A2/E^896, E^384, E^640, E^768
__device__ float g_P [(CHUNK + 1) * MAT];     // P[i] = E^i fp32, i=1..128
__device__ unsigned g_bar;                    // global barrier counter (reset by fill)
// fp16 operands, pre-tiled + pre-swizzled (XOR-8 on 16B groups) for ldmatrix:
__device__ uint4 g_PB[128 * 4 * 2048];        // B^T tiles (hi only), 16 MB
__device__ uint4 g_ZH[64 * 4 * 1024];         // A tiles (hi only), 4 MB

// ---------------------------------------------------------------------------
// Helpers
// ---------------------------------------------------------------------------
__device__ __forceinline__ uint32_t smem_u32(const void* p) {
    uint32_t a;
    asm("{ .reg .u64 t; cvta.to.shared.u64 t, %1; cvt.u32.u64 %0, t; }"
        : "=r"(a) : "l"(p));
    return a;
}
__device__ __forceinline__ void fma2(unsigned long long& d,
                                     unsigned long long a,
                                     unsigned long long b) {
    asm("fma.rn.f32x2 %0, %1, %2, %0;" : "+l"(d) : "l"(a), "l"(b));
}
__device__ __forceinline__ unsigned long long dup2(float x) {
    unsigned long long r;
    asm("mov.b64 %0, {%1, %1};" : "=l"(r) : "f"(x));
    return r;
}
__device__ __forceinline__ void ldsm4(uint32_t* r, uint32_t addr) {
    asm volatile("ldmatrix.sync.aligned.m8n8.x4.shared.b16 {%0,%1,%2,%3}, [%4];"
                 : "=r"(r[0]), "=r"(r[1]), "=r"(r[2]), "=r"(r[3]) : "r"(addr));
}
__device__ __forceinline__ void mma16816h(float* d, const uint32_t* a,
                                          uint32_t b0, uint32_t b1) {
    asm volatile(
        "mma.sync.aligned.m16n8k16.row.col.f32.f16.f16.f32 "
        "{%0,%1,%2,%3}, {%4,%5,%6,%7}, {%8,%9}, {%0,%1,%2,%3};"
        : "+f"(d[0]), "+f"(d[1]), "+f"(d[2]), "+f"(d[3])
        : "r"(a[0]), "r"(a[1]), "r"(a[2]), "r"(a[3]), "r"(b0), "r"(b1));
}
#define CP16(dst, src) \
    asm volatile("cp.async.cg.shared.global [%0], [%1], 16;" \
                 :: "r"(dst), "l"(src))
#define CP_COMMIT() asm volatile("cp.async.commit_group;" ::: "memory")
#define CP_WAIT1()  asm volatile("cp.async.wait_group 1;" ::: "memory")
#define CP_WAIT0()  asm volatile("cp.async.wait_group 0;" ::: "memory")

__device__ __forceinline__ uint32_t packh2(__half a, __half b) {
    __half_raw ar = *(__half_raw*)&a, br = *(__half_raw*)&b;
    return (uint32_t)ar.x | ((uint32_t)br.x << 16);
}

// Global barrier (monotonic counter; reset to 0 by fill_kernel each run).
__device__ __forceinline__ void gbar(unsigned& target) {
    __syncthreads();
    target += NCTA;
    if (threadIdx.x == 0) {
        __threadfence();
        atomicAdd(&g_bar, 1u);
        unsigned v;
        for (;;) {
            asm volatile("ld.global.cg.u32 %0, [%1];" : "=r"(v) : "l"(&g_bar));
            if (v >= target) break;
            __nanosleep(64);
        }
    }
    __syncthreads();
}

// ---------------------------------------------------------------------------
// 64x64x256 FFMA2 tile GEMM, BK=32 (8 iterations). .cg global loads for
// coherence across barriers. 128 threads, 8x4 microtile.
// mode 0: C = acc. mode 1 (DIAG): C = acc + c0*I + c1*A (elementwise).
// mode 2 (ZEMIT): no C; emit fp16(acc * 2^-6) A-tiles into g_ZH (swizzled).
// ---------------------------------------------------------------------------
__device__ __noinline__ void mm64(
    float (*As)[68], float (*Bs)[64],
    const float* A, const float* B, float* C,
    int bM, int bN, int mode, float c0, float c1, int zmt, int rowhalf)
{
    const int tid = threadIdx.x;
    const int tx = tid & 15, ty = tid >> 4;

    unsigned long long acc[8][2];
#pragma unroll
    for (int i = 0; i < 8; ++i) { acc[i][0] = 0ull; acc[i][1] = 0ull; }

    // A tile 64r x 32k: 4 float4/thread ; B tile 32k x 64n: 4 float4/thread
    const int a_r = tid >> 1, a_k = (tid & 1) * 16;
    const int b_k = tid >> 2, n0  = (tid & 3) * 16;

    const float* Ap = A + (size_t)(bM * 64 + a_r) * D + a_k;
    const float* Bp = B + (size_t)b_k * D + bN * 64 + n0;

    float4 pa[4], pb[4];
#pragma unroll
    for (int j = 0; j < 4; ++j) {
        pa[j] = __ldcg((const float4*)(Ap + j * 4));
        pb[j] = __ldcg((const float4*)(Bp + j * 4));
    }

    for (int kt = 0; kt < 8; ++kt) {
#pragma unroll
        for (int j = 0; j < 4; ++j) {
            As[a_k + j * 4 + 0][a_r] = pa[j].x;
            As[a_k + j * 4 + 1][a_r] = pa[j].y;
            As[a_k + j * 4 + 2][a_r] = pa[j].z;
            As[a_k + j * 4 + 3][a_r] = pa[j].w;
            *(float4*)&Bs[b_k][n0 + j * 4] = pb[j];
        }
        __syncthreads();

        if (kt < 7) {
#pragma unroll
            for (int j = 0; j < 4; ++j) {
                pa[j] = __ldcg((const float4*)(Ap + (kt + 1) * 32 + j * 4));
                pb[j] = __ldcg((const float4*)(Bp + (size_t)(kt + 1) * 32 * D + j * 4));
            }
        }

#pragma unroll
        for (int kk = 0; kk < 32; ++kk) {
            float4 a0 = *(const float4*)&As[kk][ty * 8];
            float4 a1 = *(const float4*)&As[kk][ty * 8 + 4];
            ulonglong2 bq = *(const ulonglong2*)&Bs[kk][tx * 4];
            float a[8] = {a0.x, a0.y, a0.z, a0.w, a1.x, a1.y, a1.z, a1.w};
#pragma unroll
            for (int i = 0; i < 8; ++i) {
                unsigned long long aa = dup2(a[i]);
                fma2(acc[i][0], aa, bq.x);
                fma2(acc[i][1], aa, bq.y);
            }
        }
        __syncthreads();
    }

#pragma unroll
    for (int i = 0; i < 8; ++i) {
        int row = bM * 64 + ty * 8 + i;
        int col = bN * 64 + tx * 4;
        union { ulonglong2 u; float f[4]; } v;
        v.u.x = acc[i][0]; v.u.y = acc[i][1];
        if (mode == 0) {
            *(ulonglong2*)(C + (size_t)row * D + col) = v.u;
        } else if (mode == 1) {
#pragma unroll
            for (int q = 0; q < 4; ++q) {
                float e = v.f[q] + c1 * __ldcg(g_A + (size_t)row * D + col + q);
                if (row == col + q) e += c0;
                v.f[q] = e;
            }
            *(ulonglong2*)(C + (size_t)row * D + col) = v.u;
        } else {  // ZEMIT: fp16(val * 2^-6) -> g_ZH
            __half h0 = __float2half(v.f[0] * 0.015625f);
            __half h1 = __float2half(v.f[1] * 0.015625f);
            __half h2 = __float2half(v.f[2] * 0.015625f);
            __half h3 = __float2half(v.f[3] * 0.015625f);
            int rowloc = rowhalf * 64 + ty * 8 + i;
            int g = tx >> 1;
            int du = rowloc * 8 + (g ^ (rowloc & 7));
            uint2* p = (uint2*)((char*)(g_ZH + (size_t)(zmt * 4 + bN) * 1024 + du)
                                + (tx & 1) * 8);
            *p = make_uint2(packh2(h0, h1), packh2(h2, h3));
        }
    }
}

// convB job: power p, kchunk c -> fp16(P^p[k][n] * 2^-2) transposed+swizzled
__device__ __forceinline__ void convB_job(int p, int c) {
    for (int w = threadIdx.x; w < 2048; w += 128) {
        int n = w & 255, g = w >> 8;
        const float* src = g_P + (size_t)p * MAT + (size_t)(c * 64 + g * 8) * D + n;
        __half h[8];
#pragma unroll
        for (int e = 0; e < 8; ++e)
            h[e] = __float2half(__ldcg(src + (size_t)e * D) * 0.25f);
        uint4 H;
        H.x = packh2(h[0], h[1]); H.y = packh2(h[2], h[3]);
        H.z = packh2(h[4], h[5]); H.w = packh2(h[6], h[7]);
        g_PB[(size_t)((p - 1) * 4 + c) * 2048 + n * 8 + (g ^ (n & 7))] = H;
    }
}

// z0 conv job: mtile (0..7), kchunk c -> fp16(z0 * 2^-6) tiles
__device__ __forceinline__ void convZ0_job(const float* z0, int mtile, int c) {
    for (int w = threadIdx.x; w < 1024; w += 128) {
        int row = w >> 3, g = w & 7;
        const float* src = z0 + (size_t)(mtile * 128 + row) * D + c * 64 + g * 8;
        __half h[8];
#pragma unroll
        for (int e = 0; e < 8; ++e) h[e] = __float2half(src[e] * 0.015625f);
        uint4 H;
        H.x = packh2(h[0], h[1]); H.y = packh2(h[2], h[3]);
        H.z = packh2(h[4], h[5]); H.w = packh2(h[6], h[7]);
        g_ZH[(size_t)(mtile * 4 + c) * 1024 + row * 8 + (g ^ (row & 7))] = H;
    }
}

// ---------------------------------------------------------------------------
// Persistent preamble: prep -> Horner-expm(3) -> doubling(7, convB overlapped)
// -> P256(+convB tail) -> P512 -> Q1 -> Q2 -> Z(ZEMIT)+z0conv. 15 barriers.
// ---------------------------------------------------------------------------
__global__ __launch_bounds__(128, 4)
void preamble_kernel(const float* __restrict__ z0, const float* __restrict__ kern) {
    __shared__ float As[32][68];
    __shared__ float Bs[32][64];
    const int cta = blockIdx.x;
    const int tid = threadIdx.x;
    unsigned target = 0;

    // stage 0: A = kern*DT ; D1 = I/24 + A/120 -> g_T2   (65536 thr = MAT)
    {
        int idx = cta * 128 + tid;
        float a = kern[idx] * 0.01f;
        g_A[idx] = a;
        int r = idx >> 8, c = idx & 255;
        g_T2[idx] = (r == c ? (1.f / 24.f) : 0.f) + a * (1.f / 120.f);
    }
    gbar(target);

    // stage 1: A2 = A*A -> g_X[0]
    for (int j = cta; j < 16; j += NCTA)
        mm64(As, Bs, g_A, g_A, g_X, j >> 2, j & 3, 0, 0.f, 0.f, 0, 0);
    gbar(target);

    // stage 2: D2 = A2*D1 + I/2 + A/6 -> g_T1
    for (int j = cta; j < 16; j += NCTA)
        mm64(As, Bs, g_X, g_T2, g_T1, j >> 2, j & 3, 1, 0.5f, 1.f / 6.f, 0, 0);
    gbar(target);

    // stage 3: E = A2*D2 + I + A -> g_P[1]
    for (int j = cta; j < 16; j += NCTA)
        mm64(As, Bs, g_X, g_T1, g_P + MAT, j >> 2, j & 3, 1, 1.f, 1.f, 0, 0);
    gbar(target);

    // doubling s=0..6 (m=2^s): P[m+i] = P[m]*P[i]; convB of powers (m/2, m]
    for (int s = 0; s < 7; ++s) {
        int m = 1 << s;
        int nmm = 16 * m;
        int ncv = (s == 0) ? 4 : 2 * m;
        for (int j = cta; j < nmm + ncv; j += NCTA) {
            if (j < nmm) {
                int i = 1 + (j >> 4), t = j & 15;
                mm64(As, Bs, g_P + (size_t)m * MAT, g_P + (size_t)i * MAT,
                     g_P + (size_t)(m + i) * MAT, t >> 2, t & 3, 0, 0.f, 0.f, 0, 0);
            } else {
                int e = j - nmm;
                int p = (s == 0) ? 1 : (m / 2 + 1 + (e >> 2));
                convB_job(p, e & 3);
            }
        }
        gbar(target);
    }

    // P256 = P128*P128 -> g_T2 (D1 dead)  + convB of powers 65..128
    for (int j = cta; j < 16 + 256; j += NCTA) {
        if (j < 16)
            mm64(As, Bs, g_P + (size_t)128 * MAT, g_P + (size_t)128 * MAT, g_T2,
                 j >> 2, j & 3, 0, 0.f, 0.f, 0, 0);
        else { int e = j - 16; convB_job(65 + (e >> 2), e & 3); }
    }
    gbar(target);

    // P512 = P256*P256 -> g_T1 (D2 dead)
    for (int j = cta; j < 16; j += NCTA)
        mm64(As, Bs, g_T2, g_T2, g_T1, j >> 2, j & 3, 0, 0.f, 0.f, 0, 0);
    gbar(target);

    // Q1: E^384 = P128*P256 -> X1 ; E^640 = P128*P512 -> X2 ; E^768 = P256*P512 -> X3
    for (int j = cta; j < 48; j += NCTA) {
        int q = j >> 4, t = j & 15;
        const float* Aq = (q == 2) ? g_T2 : g_P + (size_t)128 * MAT;
        const float* Bq = (q == 0) ? g_T2 : g_T1;
        mm64(As, Bs, Aq, Bq, g_X + (size_t)(q + 1) * MAT, t >> 2, t & 3, 0, 0.f, 0.f, 0, 0);
    }
    gbar(target);

    // Q2: E^896 = E^384 * P512 -> X0 (A2 dead)
    for (int j = cta; j < 16; j += NCTA)
        mm64(As, Bs, g_X + MAT, g_T1, g_X, j >> 2, j & 3, 0, 0.f, 0.f, 0, 0);
    gbar(target);

    // Z stage: Z_j = z0 * Q_j (j=1..7), fp16 emitted directly; + z0's own tiles.
    for (int j = cta; j < 480; j += NCTA) {
        if (j < 448) {
            int zj = 1 + (j >> 6), t = j & 63;
            int bM = t >> 2, bN = t & 3;
            const float* Q =
                (zj == 1) ? g_P + (size_t)128 * MAT :
                (zj == 2) ? g_T2 :
                (zj == 3) ? g_X + (size_t)1 * MAT :
                (zj == 4) ? g_T1 :
                (zj == 5) ? g_X + (size_t)2 * MAT :
                (zj == 6) ? g_X + (size_t)3 * MAT : g_X;
            mm64(As, Bs, z0, Q, nullptr, bM, bN, 2, 0.f, 0.f,
                 zj * 8 + (bM >> 1), bM & 1);
        } else {
            int e = j - 448;
            convZ0_job(z0, e >> 2, e & 3);
        }
    }
    // no final barrier: kernel boundary orders vs fill; g_bar reset by fill.
}

// ---------------------------------------------------------------------------
// HMMA fill (unchanged, at MMA floor): single-pass fp16, 2 CTAs/SM,
// double-buffered cp.async, warp tile 64x32.  Also resets g_bar for next run.
// ---------------------------------------------------------------------------
#define STAGE_BYTES 32768
#define FILL_SMEM   (2 * STAGE_BYTES)   // 64 KB

__global__ __launch_bounds__(256, 2)
void fill_kernel(float* __restrict__ out) {
    extern __shared__ __align__(128) char sm[];
    const uint32_t sbase = smem_u32(sm);
    const int tid = threadIdx.x;
    if (blockIdx.x == 0 && blockIdx.y == 0 && tid == 0) g_bar = 0;
    const int tile_m = blockIdx.x >> 1, tile_n = blockIdx.x & 1;
    const int z = blockIdx.y;
    const int wid = tid >> 5, lid = tid & 31;
    const int warp_m = wid >> 2, warp_n = wid & 3;

    auto issue = [&](int c, int buf) {
        const char* a0 = (const char*)(g_ZH + (size_t)(tile_m * 4 + c) * 1024)
                         + tid * 16;
        const char* b0 = (const char*)(g_PB + (size_t)(z * 4 + c) * 2048
                                       + tile_n * 1024) + tid * 16;
        uint32_t d = sbase + buf * STAGE_BYTES + tid * 16;
#pragma unroll
        for (int q = 0; q < 4; ++q) {
            CP16(d + q * 4096,         a0 + q * 4096);            // Ah
            CP16(d + 16384 + q * 4096, b0 + q * 4096);            // Bh
        }
        CP_COMMIT();
    };

    float acc[4][4][4];
#pragma unroll
    for (int i = 0; i < 4; ++i)
#pragma unroll
        for (int j = 0; j < 4; ++j)
#pragma unroll
            for (int q = 0; q < 4; ++q) acc[i][j][q] = 0.f;

    const int lq = lid >> 3, lr = lid & 7;
    const uint32_t a_row = warp_m * 64 + (lq & 1) * 8 + lr;
    const uint32_t b_row = warp_n * 32 + (lq & 1) * 8 + lr;
    const int gh = lq >> 1;

    issue(0, 0);
    for (int c = 0; c < 4; ++c) {
        if (c < 3) { issue(c + 1, (c + 1) & 1); CP_WAIT1(); }
        else       { CP_WAIT0(); }
        __syncthreads();

        const uint32_t ab  = sbase + (c & 1) * STAGE_BYTES;
        const uint32_t bhb = ab + 16384;
#pragma unroll
        for (int ks = 0; ks < 4; ++ks) {
            const uint32_t gx = ((uint32_t)(ks * 2 + gh) ^ lr) * 16;
            uint32_t ah[4][4], bh[2][4];
#pragma unroll
            for (int mf = 0; mf < 4; ++mf)
                ldsm4(ah[mf], ab + (a_row + mf * 16) * 128 + gx);
#pragma unroll
            for (int nf = 0; nf < 2; ++nf)
                ldsm4(bh[nf], bhb + (b_row + nf * 16) * 128 + gx);
#pragma unroll
            for (int mf = 0; mf < 4; ++mf)
#pragma unroll
                for (int j = 0; j < 4; ++j) {
                    const int n2 = j >> 1, e = j & 1;
                    mma16816h(acc[mf][j], ah[mf], bh[n2][e], bh[n2][e + 2]);
                }
        }
        __syncthreads();
    }

    // epilogue: undo operand scaling (2^-6 * 2^-2 -> x256)
    const int t  = (tile_m >> 3) * CHUNK + z;
    const int b0 = (tile_m & 7) * 128 + warp_m * 64;
    const int nb = tile_n * 128 + warp_n * 32 + (lid & 3) * 2;
    const int rr = lid >> 2;
#pragma unroll
    for (int mf = 0; mf < 4; ++mf)
#pragma unroll
        for (int j = 0; j < 4; ++j) {
            int b = b0 + mf * 16 + rr;
            float* p0 = out + ((size_t)b * TSTEPS + t) * D + nb + j * 8;
            float* p1 = out + ((size_t)(b + 8) * TSTEPS + t) * D + nb + j * 8;
            *(float2*)p0 = make_float2(acc[mf][j][0] * 256.f, acc[mf][j][1] * 256.f);
            *(float2*)p1 = make_float2(acc[mf][j][2] * 256.f, acc[mf][j][3] * 256.f);
        }
}

// ---------------------------------------------------------------------------
// Launch: persistent preamble -> fill
// ---------------------------------------------------------------------------
extern "C" void kernel_launch(void* const* d_in, const int* in_sizes, int n_in,
                              void* d_out, int out_size) {
    const float* z0   = (const float*)d_in[0];
    const float* kern = (const float*)d_in[1];
    float* out = (float*)d_out;
    (void)in_sizes; (void)n_in; (void)out_size;

    preamble_kernel<<<NCTA, 128>>>(z0, kern);

    cudaFuncSetAttribute(fill_kernel,
                         cudaFuncAttributeMaxDynamicSharedMemorySize, FILL_SMEM);
    dim3 gf(128, 128);
    fill_kernel<<<gf, 256, FILL_SMEM>>>(out);
}